// round 2
// baseline (speedup 1.0000x reference)
#include <cuda_runtime.h>
#include <math.h>

#define S_LEN 4096
#define DM    1024
#define NH    8
#define HD    128
#define NK    2048
#define EPSN  1e-6f

// ---------------- scratch (device globals; no allocation allowed) -------------
__device__ float g_q[(size_t)S_LEN * DM];            // q projection, normalized in-place
__device__ float g_knT[(size_t)NH * HD * NK];        // normalized*scaled keys, transposed per head [h][d][k]
__device__ float g_v[(size_t)NH * NK * HD];          // values regrouped per head [h][k][d]
__device__ float g_s[(size_t)NH * S_LEN * NK];       // exp(scores) [h][s][k]  (256 MB)
__device__ float g_y[(size_t)S_LEN * DM];            // attention output, heads merged
__device__ float g_denom[(size_t)NH * S_LEN];        // softmax denominators [h][s]

// ---------------- generic tiled SGEMM: C = A*B with epilogue ------------------
// EPI: 0 = plain store, 1 = store expf(acc), 2 = store acc / denom[bz*dstride + row]
// Tiles: BM=64, BN=64, BK=16, 256 threads, 4x4 per thread. All shapes here are
// exact multiples of the tiles, so no bounds checks.
template <int EPI>
__global__ void sgemm_kernel(const float* __restrict__ A, const float* __restrict__ B,
                             float* __restrict__ C,
                             int K, int lda, int ldb, int ldc,
                             long long strideA, long long strideB, long long strideC,
                             const float* __restrict__ denom, int dstride)
{
    A += (long long)blockIdx.z * strideA;
    B += (long long)blockIdx.z * strideB;
    C += (long long)blockIdx.z * strideC;

    __shared__ float As[16][65];   // padded: transposed A tile, conflict-free stores
    __shared__ float Bs[16][64];

    const int bm = blockIdx.y * 64;
    const int bn = blockIdx.x * 64;
    const int tid = threadIdx.x;
    const int tx = tid & 15;       // 0..15 -> N
    const int ty = tid >> 4;       // 0..15 -> M

    // load mapping
    const int aRow = tid >> 2;          // 0..63
    const int aK4  = (tid & 3) * 4;     // 0,4,8,12
    const int bK   = tid >> 4;          // 0..15
    const int bN4  = (tid & 15) * 4;    // 0..60

    float acc[4][4] = {};

    for (int k0 = 0; k0 < K; k0 += 16) {
        float4 av = *reinterpret_cast<const float4*>(&A[(long long)(bm + aRow) * lda + k0 + aK4]);
        As[aK4 + 0][aRow] = av.x;
        As[aK4 + 1][aRow] = av.y;
        As[aK4 + 2][aRow] = av.z;
        As[aK4 + 3][aRow] = av.w;
        float4 bv = *reinterpret_cast<const float4*>(&B[(long long)(k0 + bK) * ldb + bn + bN4]);
        *reinterpret_cast<float4*>(&Bs[bK][bN4]) = bv;
        __syncthreads();

        #pragma unroll
        for (int kk = 0; kk < 16; kk++) {
            float ar[4], br[4];
            #pragma unroll
            for (int i = 0; i < 4; i++) ar[i] = As[kk][ty * 4 + i];
            float4 b4 = *reinterpret_cast<const float4*>(&Bs[kk][tx * 4]);
            br[0] = b4.x; br[1] = b4.y; br[2] = b4.z; br[3] = b4.w;
            #pragma unroll
            for (int i = 0; i < 4; i++)
                #pragma unroll
                for (int j = 0; j < 4; j++)
                    acc[i][j] = fmaf(ar[i], br[j], acc[i][j]);
        }
        __syncthreads();
    }

    #pragma unroll
    for (int i = 0; i < 4; i++) {
        const int r = bm + ty * 4 + i;
        float inv = 1.0f;
        if (EPI == 2) inv = 1.0f / denom[blockIdx.z * dstride + r];
        float4 o;
        float v0 = acc[i][0], v1 = acc[i][1], v2 = acc[i][2], v3 = acc[i][3];
        if (EPI == 1) { v0 = expf(v0); v1 = expf(v1); v2 = expf(v2); v3 = expf(v3); }
        if (EPI == 2) { v0 *= inv; v1 *= inv; v2 *= inv; v3 *= inv; }
        o.x = v0; o.y = v1; o.z = v2; o.w = v3;
        *reinterpret_cast<float4*>(&C[(long long)r * ldc + bn + tx * 4]) = o;
    }
}

// ---------------- q row-segment L2 normalize (in place) ----------------------
// q layout: [s][h*128+d] -> segment id = s*NH + h maps to contiguous 128 floats.
__global__ void normalize_q_kernel(float* __restrict__ q)
{
    const int seg = blockIdx.x * (blockDim.x >> 5) + (threadIdx.x >> 5);
    const int lane = threadIdx.x & 31;
    if (seg >= S_LEN * NH) return;
    float4* p = reinterpret_cast<float4*>(q + (size_t)seg * HD);
    float4 v = p[lane];
    float ss = v.x * v.x + v.y * v.y + v.z * v.z + v.w * v.w;
    #pragma unroll
    for (int o = 16; o > 0; o >>= 1) ss += __shfl_xor_sync(0xffffffffu, ss, o);
    const float r = rsqrtf(ss + EPSN);
    v.x *= r; v.y *= r; v.z *= r; v.w *= r;
    p[lane] = v;
}

// ---------------- key normalize+scale+transpose, value regroup ---------------
// keys/values input row n = k*NH + h. Outputs: g_knT[h][d][k], g_v[h][k][d].
__global__ void prep_kv_kernel(const float* __restrict__ keys,
                               const float* __restrict__ values,
                               const float* __restrict__ scale)
{
    const int seg = blockIdx.x * (blockDim.x >> 5) + (threadIdx.x >> 5);
    const int lane = threadIdx.x & 31;
    if (seg >= NK * NH) return;
    const int k = seg / NH;
    const int h = seg % NH;

    float4 kv = reinterpret_cast<const float4*>(keys + (size_t)seg * HD)[lane];
    float ss = kv.x * kv.x + kv.y * kv.y + kv.z * kv.z + kv.w * kv.w;
    #pragma unroll
    for (int o = 16; o > 0; o >>= 1) ss += __shfl_xor_sync(0xffffffffu, ss, o);
    const float r = rsqrtf(ss + EPSN) * scale[h];

    float* dst = g_knT + (size_t)h * HD * NK + k;
    const int d0 = lane * 4;
    dst[(size_t)(d0 + 0) * NK] = kv.x * r;
    dst[(size_t)(d0 + 1) * NK] = kv.y * r;
    dst[(size_t)(d0 + 2) * NK] = kv.z * r;
    dst[(size_t)(d0 + 3) * NK] = kv.w * r;

    float4 vv = reinterpret_cast<const float4*>(values + (size_t)seg * HD)[lane];
    reinterpret_cast<float4*>(g_v + ((size_t)h * NK + k) * HD)[lane] = vv;
}

// ---------------- row sums of exp(scores): denom[h][s] -----------------------
__global__ void rowsum_kernel(const float* __restrict__ s, float* __restrict__ denom)
{
    const int row = blockIdx.x * (blockDim.x >> 5) + (threadIdx.x >> 5);
    const int lane = threadIdx.x & 31;
    if (row >= NH * S_LEN) return;
    const float4* p = reinterpret_cast<const float4*>(s + (size_t)row * NK);
    float sum = 0.0f;
    #pragma unroll 4
    for (int i = lane; i < NK / 4; i += 32) {
        float4 v = p[i];
        sum += (v.x + v.y) + (v.z + v.w);
    }
    #pragma unroll
    for (int o = 16; o > 0; o >>= 1) sum += __shfl_xor_sync(0xffffffffu, sum, o);
    if (lane == 0) denom[row] = sum;
}

// ---------------- launch ------------------------------------------------------
extern "C" void kernel_launch(void* const* d_in, const int* in_sizes, int n_in,
                              void* d_out, int out_size)
{
    const float* x      = (const float*)d_in[0];
    const float* Wq     = (const float*)d_in[1];
    const float* keys   = (const float*)d_in[2];
    const float* values = (const float*)d_in[3];
    const float* scale  = (const float*)d_in[4];
    const float* Wo     = (const float*)d_in[5];
    float* out = (float*)d_out;

    float *pq, *pknT, *pv, *ps, *py, *pd;
    cudaGetSymbolAddress((void**)&pq,   g_q);
    cudaGetSymbolAddress((void**)&pknT, g_knT);
    cudaGetSymbolAddress((void**)&pv,   g_v);
    cudaGetSymbolAddress((void**)&ps,   g_s);
    cudaGetSymbolAddress((void**)&py,   g_y);
    cudaGetSymbolAddress((void**)&pd,   g_denom);

    // 1) q = x @ Wq   (4096 x 1024 x 1024)
    sgemm_kernel<0><<<dim3(DM / 64, S_LEN / 64, 1), 256>>>(
        x, Wq, pq, DM, DM, DM, DM, 0, 0, 0, nullptr, 0);

    // 2) normalize q segments; prep keys/values
    normalize_q_kernel<<<(S_LEN * NH) / 8, 256>>>(pq);
    prep_kv_kernel<<<(NK * NH) / 8, 256>>>(keys, values, scale);

    // 3) exp(scores) = exp(qn @ knT)  per head: 4096 x 2048 x 128
    sgemm_kernel<1><<<dim3(NK / 64, S_LEN / 64, NH), 256>>>(
        pq, pknT, ps, HD, DM, NK, NK,
        (long long)HD, (long long)HD * NK, (long long)S_LEN * NK, nullptr, 0);

    // 4) softmax denominators
    rowsum_kernel<<<(NH * S_LEN) / 8, 256>>>(ps, pd);

    // 5) y = (P / denom) @ v  per head: 4096 x 128 x 2048, into merged-head layout
    sgemm_kernel<2><<<dim3(HD / 64, S_LEN / 64, NH), 256>>>(
        ps, pv, py, NK, NK, HD, DM,
        (long long)S_LEN * NK, (long long)NK * HD, (long long)HD, pd, S_LEN);

    // 6) out = y @ Wo  (4096 x 1024 x 1024)
    sgemm_kernel<0><<<dim3(DM / 64, S_LEN / 64, 1), 256>>>(
        py, Wo, out, DM, DM, DM, DM, 0, 0, 0, nullptr, 0);
}

// round 6
// speedup vs baseline: 1.1356x; 1.1356x over previous
#include <cuda_runtime.h>
#include <math.h>

#define S_LEN 4096
#define DM    1024
#define NH    8
#define HD    128
#define NK    2048
#define EPSN  1e-6f

// ---------------- scratch (device globals; no allocation allowed) -------------
__device__ float g_q[(size_t)S_LEN * DM];            // q projection, normalized in-place
__device__ float g_knT[(size_t)NH * HD * NK];        // normalized*scaled keys, per head [h][d][k]
__device__ float g_v[(size_t)NH * NK * HD];          // values regrouped per head [h][k][d]
__device__ float g_s[(size_t)NH * S_LEN * NK];       // exp(scores) [h][s][k]  (256 MB)
__device__ float g_y[(size_t)S_LEN * DM];            // attention output, heads merged
__device__ float g_denom[(size_t)NH * S_LEN];        // softmax denominators [h][s]

// ---------------- 128x128x16 SGEMM, 8x8 per-thread, double-buffered -----------
// EPI: 0 = plain store, 1 = store __expf(acc), 2 = store acc / denom[bz*dstride + row]
// All shapes are exact multiples of 128 in M/N and 16 in K -> no bounds checks.
template <int EPI>
__global__ void __launch_bounds__(256, 2)
sgemm128_kernel(const float* __restrict__ A, const float* __restrict__ B,
                float* __restrict__ C,
                int K, int lda, int ldb, int ldc,
                long long strideA, long long strideB, long long strideC,
                const float* __restrict__ denom, int dstride)
{
    A += (long long)blockIdx.z * strideA;
    B += (long long)blockIdx.z * strideB;
    C += (long long)blockIdx.z * strideC;

    __shared__ float As[2][16][132];   // transposed A tile [k][m], padded
    __shared__ float Bs[2][16][128];   // B tile [k][n]

    const int bm  = blockIdx.y * 128;
    const int bn  = blockIdx.x * 128;
    const int tid = threadIdx.x;
    const int tx  = tid & 15;          // 0..15 -> N (8 cols each)
    const int ty  = tid >> 4;          // 0..15 -> M (8 rows each)

    // global load mapping:
    // A: thread loads 8 contiguous floats from one row:  row = tid>>1, k offset = (tid&1)*8
    const int aRow = tid >> 1;
    const int aK   = (tid & 1) * 8;
    // B: thread loads 8 contiguous floats from one row:  k = tid>>4, n offset = (tid&15)*8
    const int bRow = tid >> 4;
    const int bCol = (tid & 15) * 8;

    const float* Aptr = A + (long long)(bm + aRow) * lda + aK;
    const float* Bptr = B + (long long)bRow * ldb + bn + bCol;

    const int nT = K / 16;

    float4 sa0, sa1, sb0, sb1;

    // prologue: tile 0 -> buf 0
    sa0 = *reinterpret_cast<const float4*>(Aptr);
    sa1 = *reinterpret_cast<const float4*>(Aptr + 4);
    sb0 = *reinterpret_cast<const float4*>(Bptr);
    sb1 = *reinterpret_cast<const float4*>(Bptr + 4);
    As[0][aK + 0][aRow] = sa0.x;  As[0][aK + 1][aRow] = sa0.y;
    As[0][aK + 2][aRow] = sa0.z;  As[0][aK + 3][aRow] = sa0.w;
    As[0][aK + 4][aRow] = sa1.x;  As[0][aK + 5][aRow] = sa1.y;
    As[0][aK + 6][aRow] = sa1.z;  As[0][aK + 7][aRow] = sa1.w;
    *reinterpret_cast<float4*>(&Bs[0][bRow][bCol])     = sb0;
    *reinterpret_cast<float4*>(&Bs[0][bRow][bCol + 4]) = sb1;
    __syncthreads();

    float acc[8][8] = {};

    for (int t = 0; t < nT; t++) {
        const int cur = t & 1;

        if (t + 1 < nT) {
            const float* Ap = Aptr + (t + 1) * 16;
            const float* Bp = Bptr + (long long)(t + 1) * 16 * ldb;
            sa0 = *reinterpret_cast<const float4*>(Ap);
            sa1 = *reinterpret_cast<const float4*>(Ap + 4);
            sb0 = *reinterpret_cast<const float4*>(Bp);
            sb1 = *reinterpret_cast<const float4*>(Bp + 4);
        }

        #pragma unroll
        for (int kk = 0; kk < 16; kk++) {
            float a[8], b[8];
            float4 t0 = *reinterpret_cast<const float4*>(&As[cur][kk][ty * 8]);
            float4 t1 = *reinterpret_cast<const float4*>(&As[cur][kk][ty * 8 + 4]);
            a[0]=t0.x; a[1]=t0.y; a[2]=t0.z; a[3]=t0.w;
            a[4]=t1.x; a[5]=t1.y; a[6]=t1.z; a[7]=t1.w;
            float4 u0 = *reinterpret_cast<const float4*>(&Bs[cur][kk][tx * 8]);
            float4 u1 = *reinterpret_cast<const float4*>(&Bs[cur][kk][tx * 8 + 4]);
            b[0]=u0.x; b[1]=u0.y; b[2]=u0.z; b[3]=u0.w;
            b[4]=u1.x; b[5]=u1.y; b[6]=u1.z; b[7]=u1.w;
            #pragma unroll
            for (int i = 0; i < 8; i++)
                #pragma unroll
                for (int j = 0; j < 8; j++)
                    acc[i][j] = fmaf(a[i], b[j], acc[i][j]);
        }

        if (t + 1 < nT) {
            const int nxt = cur ^ 1;
            As[nxt][aK + 0][aRow] = sa0.x;  As[nxt][aK + 1][aRow] = sa0.y;
            As[nxt][aK + 2][aRow] = sa0.z;  As[nxt][aK + 3][aRow] = sa0.w;
            As[nxt][aK + 4][aRow] = sa1.x;  As[nxt][aK + 5][aRow] = sa1.y;
            As[nxt][aK + 6][aRow] = sa1.z;  As[nxt][aK + 7][aRow] = sa1.w;
            *reinterpret_cast<float4*>(&Bs[nxt][bRow][bCol])     = sb0;
            *reinterpret_cast<float4*>(&Bs[nxt][bRow][bCol + 4]) = sb1;
        }
        __syncthreads();
    }

    // epilogue
    #pragma unroll
    for (int i = 0; i < 8; i++) {
        const int r = bm + ty * 8 + i;
        float inv = 1.0f;
        if (EPI == 2) inv = 1.0f / denom[blockIdx.z * dstride + r];
        float v[8];
        #pragma unroll
        for (int j = 0; j < 8; j++) {
            float t = acc[i][j];
            if (EPI == 1) t = __expf(t);
            if (EPI == 2) t *= inv;
            v[j] = t;
        }
        float4 o0 = make_float4(v[0], v[1], v[2], v[3]);
        float4 o1 = make_float4(v[4], v[5], v[6], v[7]);
        float* cp = &C[(long long)r * ldc + bn + tx * 8];
        *reinterpret_cast<float4*>(cp)     = o0;
        *reinterpret_cast<float4*>(cp + 4) = o1;
    }
}

// ---------------- q row-segment L2 normalize (in place) ----------------------
__global__ void normalize_q_kernel(float* __restrict__ q)
{
    const int seg = blockIdx.x * (blockDim.x >> 5) + (threadIdx.x >> 5);
    const int lane = threadIdx.x & 31;
    if (seg >= S_LEN * NH) return;
    float4* p = reinterpret_cast<float4*>(q + (size_t)seg * HD);
    float4 v = p[lane];
    float ss = v.x * v.x + v.y * v.y + v.z * v.z + v.w * v.w;
    #pragma unroll
    for (int o = 16; o > 0; o >>= 1) ss += __shfl_xor_sync(0xffffffffu, ss, o);
    const float r = rsqrtf(ss + EPSN);
    v.x *= r; v.y *= r; v.z *= r; v.w *= r;
    p[lane] = v;
}

// ---------------- key normalize+scale+transpose, value regroup ---------------
__global__ void prep_kv_kernel(const float* __restrict__ keys,
                               const float* __restrict__ values,
                               const float* __restrict__ scale)
{
    const int seg = blockIdx.x * (blockDim.x >> 5) + (threadIdx.x >> 5);
    const int lane = threadIdx.x & 31;
    if (seg >= NK * NH) return;
    const int k = seg / NH;
    const int h = seg % NH;

    float4 kv = reinterpret_cast<const float4*>(keys + (size_t)seg * HD)[lane];
    float ss = kv.x * kv.x + kv.y * kv.y + kv.z * kv.z + kv.w * kv.w;
    #pragma unroll
    for (int o = 16; o > 0; o >>= 1) ss += __shfl_xor_sync(0xffffffffu, ss, o);
    const float r = rsqrtf(ss + EPSN) * scale[h];

    float* dst = g_knT + (size_t)h * HD * NK + k;
    const int d0 = lane * 4;
    dst[(size_t)(d0 + 0) * NK] = kv.x * r;
    dst[(size_t)(d0 + 1) * NK] = kv.y * r;
    dst[(size_t)(d0 + 2) * NK] = kv.z * r;
    dst[(size_t)(d0 + 3) * NK] = kv.w * r;

    float4 vv = reinterpret_cast<const float4*>(values + (size_t)seg * HD)[lane];
    reinterpret_cast<float4*>(g_v + ((size_t)h * NK + k) * HD)[lane] = vv;
}

// ---------------- row sums of exp(scores): denom[h][s] -----------------------
__global__ void rowsum_kernel(const float* __restrict__ s, float* __restrict__ denom)
{
    const int row = blockIdx.x * (blockDim.x >> 5) + (threadIdx.x >> 5);
    const int lane = threadIdx.x & 31;
    if (row >= NH * S_LEN) return;
    const float4* p = reinterpret_cast<const float4*>(s + (size_t)row * NK);
    float sum = 0.0f;
    #pragma unroll 4
    for (int i = lane; i < NK / 4; i += 32) {
        float4 v = p[i];
        sum += (v.x + v.y) + (v.z + v.w);
    }
    #pragma unroll
    for (int o = 16; o > 0; o >>= 1) sum += __shfl_xor_sync(0xffffffffu, sum, o);
    if (lane == 0) denom[row] = sum;
}

// ---------------- launch ------------------------------------------------------
extern "C" void kernel_launch(void* const* d_in, const int* in_sizes, int n_in,
                              void* d_out, int out_size)
{
    const float* x      = (const float*)d_in[0];
    const float* Wq     = (const float*)d_in[1];
    const float* keys   = (const float*)d_in[2];
    const float* values = (const float*)d_in[3];
    const float* scale  = (const float*)d_in[4];
    const float* Wo     = (const float*)d_in[5];
    float* out = (float*)d_out;

    float *pq, *pknT, *pv, *ps, *py, *pd;
    cudaGetSymbolAddress((void**)&pq,   g_q);
    cudaGetSymbolAddress((void**)&pknT, g_knT);
    cudaGetSymbolAddress((void**)&pv,   g_v);
    cudaGetSymbolAddress((void**)&ps,   g_s);
    cudaGetSymbolAddress((void**)&py,   g_y);
    cudaGetSymbolAddress((void**)&pd,   g_denom);

    // 1) q = x @ Wq   (4096 x 1024 x 1024)
    sgemm128_kernel<0><<<dim3(DM / 128, S_LEN / 128, 1), 256>>>(
        x, Wq, pq, DM, DM, DM, DM, 0, 0, 0, nullptr, 0);

    // 2) normalize q segments; prep keys/values
    normalize_q_kernel<<<(S_LEN * NH) / 8, 256>>>(pq);
    prep_kv_kernel<<<(NK * NH) / 8, 256>>>(keys, values, scale);

    // 3) exp(scores) = exp(qn @ knT)  per head: 4096 x 2048 x 128
    sgemm128_kernel<1><<<dim3(NK / 128, S_LEN / 128, NH), 256>>>(
        pq, pknT, ps, HD, DM, NK, NK,
        (long long)HD, (long long)HD * NK, (long long)S_LEN * NK, nullptr, 0);

    // 4) softmax denominators
    rowsum_kernel<<<(NH * S_LEN) / 8, 256>>>(ps, pd);

    // 5) y = (P / denom) @ v  per head: 4096 x 128 x 2048, into merged-head layout
    sgemm128_kernel<2><<<dim3(HD / 128, S_LEN / 128, NH), 256>>>(
        ps, pv, py, NK, NK, HD, DM,
        (long long)S_LEN * NK, (long long)NK * HD, (long long)HD, pd, S_LEN);

    // 6) out = y @ Wo  (4096 x 1024 x 1024)
    sgemm128_kernel<0><<<dim3(DM / 128, S_LEN / 128, 1), 256>>>(
        py, Wo, out, DM, DM, DM, DM, 0, 0, 0, nullptr, 0);
}

// round 9
// speedup vs baseline: 2.7492x; 2.4211x over previous
#include <cuda_runtime.h>
#include <cuda_bf16.h>
#include <cstdint>
#include <math.h>

#define S_LEN 4096
#define DM    1024
#define NH    8
#define HD    128
#define NK    2048
#define EPSN  1e-6f

// ---------------- scratch (device globals; no allocation allowed) -------------
__device__ __nv_bfloat16 g_xh[(size_t)S_LEN * DM], g_xl[(size_t)S_LEN * DM];
__device__ __nv_bfloat16 g_wqh[(size_t)DM * DM],   g_wql[(size_t)DM * DM];
__device__ __nv_bfloat16 g_woh[(size_t)DM * DM],   g_wol[(size_t)DM * DM];
__device__ float         g_q[(size_t)S_LEN * DM];
__device__ __nv_bfloat16 g_qnh[(size_t)S_LEN * DM], g_qnl[(size_t)S_LEN * DM];
__device__ __nv_bfloat16 g_knh[(size_t)NH * NK * HD], g_knl[(size_t)NH * NK * HD];
__device__ __nv_bfloat16 g_vth[(size_t)NH * HD * NK], g_vtl[(size_t)NH * HD * NK];
__device__ __nv_bfloat16 g_ph[(size_t)NH * S_LEN * NK], g_pl[(size_t)NH * S_LEN * NK];
__device__ __nv_bfloat16 g_yh[(size_t)S_LEN * DM], g_yl[(size_t)S_LEN * DM];
__device__ float         g_denom[(size_t)NH * S_LEN];

// ---------------- helpers -----------------------------------------------------
__device__ __forceinline__ uint32_t s2u(const void* p) {
    uint32_t a;
    asm("{ .reg .u64 t; cvta.to.shared.u64 t, %1; cvt.u32.u64 %0, t; }" : "=r"(a) : "l"(p));
    return a;
}
__device__ __forceinline__ float bfhi(float x) { return __bfloat162float(__float2bfloat16_rn(x)); }
__device__ __forceinline__ uint32_t packbf2(float a, float b) {
    __nv_bfloat162 t = __floats2bfloat162_rn(a, b);
    return reinterpret_cast<uint32_t&>(t);
}
__device__ __forceinline__ void cpasync16(uint32_t dst, const void* src) {
    asm volatile("cp.async.cg.shared.global [%0], [%1], 16;" :: "r"(dst), "l"(src));
}
__device__ __forceinline__ void ldsm4(uint32_t* r, uint32_t addr) {
    asm volatile("ldmatrix.sync.aligned.m8n8.x4.shared.b16 {%0,%1,%2,%3}, [%4];"
        : "=r"(r[0]), "=r"(r[1]), "=r"(r[2]), "=r"(r[3]) : "r"(addr));
}
__device__ __forceinline__ void mma16816(float* c, const uint32_t* a, const uint32_t* b) {
    asm volatile("mma.sync.aligned.m16n8k16.row.col.f32.bf16.bf16.f32 "
        "{%0,%1,%2,%3}, {%4,%5,%6,%7}, {%8,%9}, {%0,%1,%2,%3};"
        : "+f"(c[0]), "+f"(c[1]), "+f"(c[2]), "+f"(c[3])
        : "r"(a[0]), "r"(a[1]), "r"(a[2]), "r"(a[3]), "r"(b[0]), "r"(b[1]));
}

// ---------------- HMMA bf16-split GEMM: C = A * B^T (3 passes) ----------------
// A[hi/lo]: [M][K] bf16 row-major; B[hi/lo]: [N][K] bf16 (K contiguous).
// CTA 128x128, BK=32, 8 warps (warp tile 64x32), 2-stage cp.async pipeline.
// EPI 0: fp32 store; 1: exp -> bf16 hi/lo + atomic rowsum; 2: /denom -> bf16 hi/lo.
#define ROWB  80                 // 32 bf16 + 8 pad = 80 bytes per smem row
#define TILEB (128 * ROWB)       // 10240 B per tile
#define SMEM_TOT (8 * TILEB)     // 2 stages x 4 arrays

template <int EPI>
__global__ void __launch_bounds__(256, 2)
mma_gemm(const __nv_bfloat16* __restrict__ Ah, const __nv_bfloat16* __restrict__ Al,
         const __nv_bfloat16* __restrict__ Bh, const __nv_bfloat16* __restrict__ Bl,
         void* __restrict__ C0, void* __restrict__ C1,
         int K, int lda, int ldb, int ldc,
         long long sA, long long sB, long long sC,
         float* __restrict__ denom, int dstride)
{
    extern __shared__ char smch[];
    const uint32_t smb = s2u(smch);
    const int tid = threadIdx.x, lane = tid & 31, wid = tid >> 5;
    const int warpM = wid & 1, warpN = wid >> 1;
    const int bm = blockIdx.y * 128, bn = blockIdx.x * 128;
    const long long z = blockIdx.z;

    const __nv_bfloat16* src[4];
    src[0] = Ah + z * sA + (long long)bm * lda;
    src[1] = Al + z * sA + (long long)bm * lda;
    src[2] = Bh + z * sB + (long long)bn * ldb;
    src[3] = Bl + z * sB + (long long)bn * ldb;

    // ldmatrix per-lane offsets
    const int aLR = (lane & 7) + ((lane >> 3) & 1) * 8;  // m row within 16
    const int aLK = (lane >> 4) * 8;                     // k half
    const int bLR = (lane & 7) + (lane >> 4) * 8;        // n row within 16
    const int bLK = ((lane >> 3) & 1) * 8;               // k half
    int aOff[4], bOff[2];
    #pragma unroll
    for (int m = 0; m < 4; m++) aOff[m] = (warpM * 64 + m * 16 + aLR) * ROWB + aLK * 2;
    #pragma unroll
    for (int p = 0; p < 2; p++) bOff[p] = (warpN * 32 + p * 16 + bLR) * ROWB + bLK * 2;

    float acc[4][4][4] = {};
    const int nCh = K >> 5;

    // global->smem stage loader (cp.async, 16B chunks)
    auto load_stage = [&](int st, int k0) {
        #pragma unroll
        for (int w = 0; w < 4; w++) {
            const __nv_bfloat16* s = src[w] + k0;
            const int ld = (w < 2) ? lda : ldb;
            const uint32_t dst = smb + (uint32_t)(st * 4 + w) * TILEB;
            #pragma unroll
            for (int i = 0; i < 2; i++) {
                const int u = tid + i * 256;
                const int row = u >> 2, c = u & 3;
                cpasync16(dst + row * ROWB + c * 16, s + (long long)row * ld + c * 8);
            }
        }
    };

    load_stage(0, 0);
    asm volatile("cp.async.commit_group;" ::: "memory");

    for (int t = 0; t < nCh; t++) {
        if (t + 1 < nCh) {
            load_stage((t + 1) & 1, (t + 1) * 32);
            asm volatile("cp.async.commit_group;" ::: "memory");
            asm volatile("cp.async.wait_group 1;" ::: "memory");
        } else {
            asm volatile("cp.async.wait_group 0;" ::: "memory");
        }
        __syncthreads();

        const uint32_t base = smb + (uint32_t)((t & 1) * 4) * TILEB;
        #pragma unroll
        for (int kk = 0; kk < 2; kk++) {
            uint32_t bh[8], bl[8];
            #pragma unroll
            for (int p = 0; p < 2; p++) {
                ldsm4(bh + 4 * p, base + 2 * TILEB + bOff[p] + kk * 32);
                ldsm4(bl + 4 * p, base + 3 * TILEB + bOff[p] + kk * 32);
            }
            #pragma unroll
            for (int m = 0; m < 4; m++) {
                uint32_t ah[4], al[4];
                ldsm4(ah, base + 0 * TILEB + aOff[m] + kk * 32);
                ldsm4(al, base + 1 * TILEB + aOff[m] + kk * 32);
                #pragma unroll
                for (int n = 0; n < 4; n++) {
                    mma16816(acc[m][n], ah, bh + 2 * n);
                    mma16816(acc[m][n], ah, bl + 2 * n);
                    mma16816(acc[m][n], al, bh + 2 * n);
                }
            }
        }
        __syncthreads();
    }

    // ---------------- epilogue ----------------
    const int qr = lane >> 2, qc = (lane & 3) * 2;
    #pragma unroll
    for (int m = 0; m < 4; m++) {
        const int r0 = bm + warpM * 64 + m * 16 + qr;
        const int r1 = r0 + 8;
        if (EPI == 0) {
            float* C = (float*)C0 + z * sC;
            #pragma unroll
            for (int n = 0; n < 4; n++) {
                const int c = bn + warpN * 32 + n * 8 + qc;
                *reinterpret_cast<float2*>(C + (long long)r0 * ldc + c) =
                    make_float2(acc[m][n][0], acc[m][n][1]);
                *reinterpret_cast<float2*>(C + (long long)r1 * ldc + c) =
                    make_float2(acc[m][n][2], acc[m][n][3]);
            }
        } else if (EPI == 1) {
            __nv_bfloat16* Ph = (__nv_bfloat16*)C0 + z * sC;
            __nv_bfloat16* Pl = (__nv_bfloat16*)C1 + z * sC;
            float s0 = 0.0f, s1 = 0.0f;
            #pragma unroll
            for (int n = 0; n < 4; n++) {
                const int c = bn + warpN * 32 + n * 8 + qc;
                float e0 = __expf(acc[m][n][0]), e1 = __expf(acc[m][n][1]);
                float e2 = __expf(acc[m][n][2]), e3 = __expf(acc[m][n][3]);
                s0 += e0 + e1;  s1 += e2 + e3;
                float h0 = bfhi(e0), h1 = bfhi(e1), h2 = bfhi(e2), h3 = bfhi(e3);
                *reinterpret_cast<uint32_t*>(Ph + (long long)r0 * ldc + c) = packbf2(h0, h1);
                *reinterpret_cast<uint32_t*>(Pl + (long long)r0 * ldc + c) = packbf2(e0 - h0, e1 - h1);
                *reinterpret_cast<uint32_t*>(Ph + (long long)r1 * ldc + c) = packbf2(h2, h3);
                *reinterpret_cast<uint32_t*>(Pl + (long long)r1 * ldc + c) = packbf2(e2 - h2, e3 - h3);
            }
            s0 += __shfl_xor_sync(0xffffffffu, s0, 1);
            s0 += __shfl_xor_sync(0xffffffffu, s0, 2);
            s1 += __shfl_xor_sync(0xffffffffu, s1, 1);
            s1 += __shfl_xor_sync(0xffffffffu, s1, 2);
            if ((lane & 3) == 0) {
                atomicAdd(denom + z * dstride + r0, s0);
                atomicAdd(denom + z * dstride + r1, s1);
            }
        } else {
            __nv_bfloat16* Yh = (__nv_bfloat16*)C0 + z * sC;
            __nv_bfloat16* Yl = (__nv_bfloat16*)C1 + z * sC;
            const float inv0 = 1.0f / denom[z * dstride + r0];
            const float inv1 = 1.0f / denom[z * dstride + r1];
            #pragma unroll
            for (int n = 0; n < 4; n++) {
                const int c = bn + warpN * 32 + n * 8 + qc;
                float e0 = acc[m][n][0] * inv0, e1 = acc[m][n][1] * inv0;
                float e2 = acc[m][n][2] * inv1, e3 = acc[m][n][3] * inv1;
                float h0 = bfhi(e0), h1 = bfhi(e1), h2 = bfhi(e2), h3 = bfhi(e3);
                *reinterpret_cast<uint32_t*>(Yh + (long long)r0 * ldc + c) = packbf2(h0, h1);
                *reinterpret_cast<uint32_t*>(Yl + (long long)r0 * ldc + c) = packbf2(e0 - h0, e1 - h1);
                *reinterpret_cast<uint32_t*>(Yh + (long long)r1 * ldc + c) = packbf2(h2, h3);
                *reinterpret_cast<uint32_t*>(Yl + (long long)r1 * ldc + c) = packbf2(e2 - h2, e3 - h3);
            }
        }
    }
}

// ---------------- prep kernels ------------------------------------------------
__global__ void zero_kernel(float* __restrict__ p, int n)
{
    const int i = blockIdx.x * 256 + threadIdx.x;
    if (i < n) p[i] = 0.0f;
}

__global__ void split4_kernel(const float* __restrict__ s, __nv_bfloat16* __restrict__ h,
                              __nv_bfloat16* __restrict__ l, int n4)
{
    const int i = blockIdx.x * 256 + threadIdx.x;
    if (i >= n4) return;
    float4 x = reinterpret_cast<const float4*>(s)[i];
    float ha = bfhi(x.x), hb = bfhi(x.y), hc = bfhi(x.z), hd = bfhi(x.w);
    reinterpret_cast<uint2*>(h)[i] = make_uint2(packbf2(ha, hb), packbf2(hc, hd));
    reinterpret_cast<uint2*>(l)[i] = make_uint2(packbf2(x.x - ha, x.y - hb), packbf2(x.z - hc, x.w - hd));
}

__global__ void transpose_split_kernel(const float* __restrict__ W, __nv_bfloat16* __restrict__ Th,
                                       __nv_bfloat16* __restrict__ Tl, int R, int C)
{
    __shared__ float tile[32][33];
    const int r0 = blockIdx.y * 32, c0 = blockIdx.x * 32;
    for (int i = threadIdx.y; i < 32; i += 8)
        tile[i][threadIdx.x] = W[(long long)(r0 + i) * C + c0 + threadIdx.x];
    __syncthreads();
    for (int i = threadIdx.y; i < 32; i += 8) {
        float x = tile[threadIdx.x][i];
        float hh = bfhi(x);
        long long o = (long long)(c0 + i) * R + r0 + threadIdx.x;
        Th[o] = __float2bfloat16_rn(x);
        Tl[o] = __float2bfloat16_rn(x - hh);
    }
}

__global__ void normalize_q_split_kernel(const float* __restrict__ q,
                                         __nv_bfloat16* __restrict__ qh, __nv_bfloat16* __restrict__ ql)
{
    const int seg = blockIdx.x * 8 + (threadIdx.x >> 5);
    const int lane = threadIdx.x & 31;
    float4 x = reinterpret_cast<const float4*>(q + (size_t)seg * HD)[lane];
    float ss = x.x * x.x + x.y * x.y + x.z * x.z + x.w * x.w;
    #pragma unroll
    for (int o = 16; o > 0; o >>= 1) ss += __shfl_xor_sync(0xffffffffu, ss, o);
    const float rr = rsqrtf(ss + EPSN);
    float a = x.x * rr, b = x.y * rr, cc = x.z * rr, d = x.w * rr;
    float ha = bfhi(a), hb = bfhi(b), hc = bfhi(cc), hd = bfhi(d);
    reinterpret_cast<uint2*>(qh + (size_t)seg * HD)[lane] = make_uint2(packbf2(ha, hb), packbf2(hc, hd));
    reinterpret_cast<uint2*>(ql + (size_t)seg * HD)[lane] =
        make_uint2(packbf2(a - ha, b - hb), packbf2(cc - hc, d - hd));
}

__global__ void prep_k_kernel(const float* __restrict__ keys, const float* __restrict__ scale,
                              __nv_bfloat16* __restrict__ kh, __nv_bfloat16* __restrict__ kl)
{
    const int seg = blockIdx.x * 8 + (threadIdx.x >> 5);
    const int lane = threadIdx.x & 31;
    const int k = seg / NH, h = seg % NH;
    float4 x = reinterpret_cast<const float4*>(keys + (size_t)seg * HD)[lane];
    float ss = x.x * x.x + x.y * x.y + x.z * x.z + x.w * x.w;
    #pragma unroll
    for (int o = 16; o > 0; o >>= 1) ss += __shfl_xor_sync(0xffffffffu, ss, o);
    const float rr = rsqrtf(ss + EPSN) * scale[h];
    float a = x.x * rr, b = x.y * rr, cc = x.z * rr, d = x.w * rr;
    float ha = bfhi(a), hb = bfhi(b), hc = bfhi(cc), hd = bfhi(d);
    const size_t base = ((size_t)h * NK + k) * HD;
    reinterpret_cast<uint2*>(kh + base)[lane] = make_uint2(packbf2(ha, hb), packbf2(hc, hd));
    reinterpret_cast<uint2*>(kl + base)[lane] =
        make_uint2(packbf2(a - ha, b - hb), packbf2(cc - hc, d - hd));
}

__global__ void prep_v_kernel(const float* __restrict__ values,
                              __nv_bfloat16* __restrict__ vh, __nv_bfloat16* __restrict__ vl)
{
    __shared__ float tile[32][33];
    const int h = blockIdx.z, k0 = blockIdx.x * 32, d0 = blockIdx.y * 32;
    for (int i = threadIdx.y; i < 32; i += 8)
        tile[i][threadIdx.x] = values[((size_t)(k0 + i) * NH + h) * HD + d0 + threadIdx.x];
    __syncthreads();
    for (int i = threadIdx.y; i < 32; i += 8) {
        float x = tile[threadIdx.x][i];
        float hh = bfhi(x);
        size_t o = ((size_t)h * HD + d0 + i) * NK + k0 + threadIdx.x;
        vh[o] = __float2bfloat16_rn(x);
        vl[o] = __float2bfloat16_rn(x - hh);
    }
}

// ---------------- launch ------------------------------------------------------
extern "C" void kernel_launch(void* const* d_in, const int* in_sizes, int n_in,
                              void* d_out, int out_size)
{
    const float* x      = (const float*)d_in[0];
    const float* Wq     = (const float*)d_in[1];
    const float* keys   = (const float*)d_in[2];
    const float* values = (const float*)d_in[3];
    const float* scale  = (const float*)d_in[4];
    const float* Wo     = (const float*)d_in[5];
    float* out = (float*)d_out;

    __nv_bfloat16 *pxh, *pxl, *pwqh, *pwql, *pwoh, *pwol, *pqnh, *pqnl;
    __nv_bfloat16 *pkh, *pkl, *pvh, *pvl, *pph, *ppl, *pyh, *pyl;
    float *pq, *pd;
    cudaGetSymbolAddress((void**)&pxh, g_xh);   cudaGetSymbolAddress((void**)&pxl, g_xl);
    cudaGetSymbolAddress((void**)&pwqh, g_wqh); cudaGetSymbolAddress((void**)&pwql, g_wql);
    cudaGetSymbolAddress((void**)&pwoh, g_woh); cudaGetSymbolAddress((void**)&pwol, g_wol);
    cudaGetSymbolAddress((void**)&pqnh, g_qnh); cudaGetSymbolAddress((void**)&pqnl, g_qnl);
    cudaGetSymbolAddress((void**)&pkh, g_knh);  cudaGetSymbolAddress((void**)&pkl, g_knl);
    cudaGetSymbolAddress((void**)&pvh, g_vth);  cudaGetSymbolAddress((void**)&pvl, g_vtl);
    cudaGetSymbolAddress((void**)&pph, g_ph);   cudaGetSymbolAddress((void**)&ppl, g_pl);
    cudaGetSymbolAddress((void**)&pyh, g_yh);   cudaGetSymbolAddress((void**)&pyl, g_yl);
    cudaGetSymbolAddress((void**)&pq, g_q);     cudaGetSymbolAddress((void**)&pd, g_denom);

    cudaFuncSetAttribute(mma_gemm<0>, cudaFuncAttributeMaxDynamicSharedMemorySize, SMEM_TOT);
    cudaFuncSetAttribute(mma_gemm<1>, cudaFuncAttributeMaxDynamicSharedMemorySize, SMEM_TOT);
    cudaFuncSetAttribute(mma_gemm<2>, cudaFuncAttributeMaxDynamicSharedMemorySize, SMEM_TOT);

    // prep: splits and transposes
    split4_kernel<<<(S_LEN * DM / 4 + 255) / 256, 256>>>(x, pxh, pxl, S_LEN * DM / 4);
    transpose_split_kernel<<<dim3(DM / 32, DM / 32), dim3(32, 8)>>>(Wq, pwqh, pwql, DM, DM);
    transpose_split_kernel<<<dim3(DM / 32, DM / 32), dim3(32, 8)>>>(Wo, pwoh, pwol, DM, DM);
    prep_k_kernel<<<(NK * NH) / 8, 256>>>(keys, scale, pkh, pkl);
    prep_v_kernel<<<dim3(NK / 32, HD / 32, NH), dim3(32, 8)>>>(values, pvh, pvl);
    zero_kernel<<<(NH * S_LEN + 255) / 256, 256>>>(pd, NH * S_LEN);

    // 1) q = x @ Wq  (fp32 out)
    mma_gemm<0><<<dim3(DM / 128, S_LEN / 128, 1), 256, SMEM_TOT>>>(
        pxh, pxl, pwqh, pwql, pq, nullptr, DM, DM, DM, DM, 0, 0, 0, nullptr, 0);

    // 2) normalize q, split to bf16
    normalize_q_split_kernel<<<(S_LEN * NH) / 8, 256>>>(pq, pqnh, pqnl);

    // 3) exp(scores) with fused atomic rowsum
    mma_gemm<1><<<dim3(NK / 128, S_LEN / 128, NH), 256, SMEM_TOT>>>(
        pqnh, pqnl, pkh, pkl, pph, ppl,
        HD, DM, HD, NK,
        (long long)HD, (long long)NK * HD, (long long)S_LEN * NK, pd, S_LEN);

    // 4) y = (P @ v) / denom  -> bf16 hi/lo, merged-head layout
    mma_gemm<2><<<dim3(HD / 128, S_LEN / 128, NH), 256, SMEM_TOT>>>(
        pph, ppl, pvh, pvl, pyh, pyl,
        NK, NK, NK, DM,
        (long long)S_LEN * NK, (long long)HD * NK, (long long)HD, pd, S_LEN);

    // 5) out = y @ Wo  (fp32 out)
    mma_gemm<0><<<dim3(DM / 128, S_LEN / 128, 1), 256, SMEM_TOT>>>(
        pyh, pyl, pwoh, pwol, out, nullptr, DM, DM, DM, DM, 0, 0, 0, nullptr, 0);
}

// round 10
// speedup vs baseline: 3.3044x; 1.2019x over previous
#include <cuda_runtime.h>
#include <cuda_bf16.h>
#include <cstdint>
#include <math.h>

#define S_LEN 4096
#define DM    1024
#define NH    8
#define HD    128
#define NK    2048
#define EPSN  1e-6f

// ---------------- scratch (device globals; no allocation allowed) -------------
__device__ __nv_bfloat16 g_xh[(size_t)S_LEN * DM], g_xl[(size_t)S_LEN * DM];
__device__ __nv_bfloat16 g_wqh[(size_t)DM * DM],   g_wql[(size_t)DM * DM];
__device__ __nv_bfloat16 g_woh[(size_t)DM * DM],   g_wol[(size_t)DM * DM];
__device__ float         g_q[(size_t)S_LEN * DM];
__device__ __nv_bfloat16 g_qnh[(size_t)S_LEN * DM], g_qnl[(size_t)S_LEN * DM];
__device__ __nv_bfloat16 g_knh[(size_t)NH * NK * HD], g_knl[(size_t)NH * NK * HD];
__device__ __nv_bfloat16 g_vth[(size_t)NH * HD * NK], g_vtl[(size_t)NH * HD * NK];
__device__ __nv_bfloat16 g_yh[(size_t)S_LEN * DM], g_yl[(size_t)S_LEN * DM];

// ---------------- helpers -----------------------------------------------------
__device__ __forceinline__ uint32_t s2u(const void* p) {
    uint32_t a;
    asm("{ .reg .u64 t; cvta.to.shared.u64 t, %1; cvt.u32.u64 %0, t; }" : "=r"(a) : "l"(p));
    return a;
}
__device__ __forceinline__ float bfhi(float x) { return __bfloat162float(__float2bfloat16_rn(x)); }
__device__ __forceinline__ uint32_t packbf2(float a, float b) {
    __nv_bfloat162 t = __floats2bfloat162_rn(a, b);
    return reinterpret_cast<uint32_t&>(t);
}
__device__ __forceinline__ void cpasync16(uint32_t dst, const void* src) {
    asm volatile("cp.async.cg.shared.global [%0], [%1], 16;" :: "r"(dst), "l"(src));
}
__device__ __forceinline__ void ldsm4(uint32_t* r, uint32_t addr) {
    asm volatile("ldmatrix.sync.aligned.m8n8.x4.shared.b16 {%0,%1,%2,%3}, [%4];"
        : "=r"(r[0]), "=r"(r[1]), "=r"(r[2]), "=r"(r[3]) : "r"(addr));
}
__device__ __forceinline__ void mma16816(float* c, const uint32_t* a, const uint32_t* b) {
    asm volatile("mma.sync.aligned.m16n8k16.row.col.f32.bf16.bf16.f32 "
        "{%0,%1,%2,%3}, {%4,%5,%6,%7}, {%8,%9}, {%0,%1,%2,%3};"
        : "+f"(c[0]), "+f"(c[1]), "+f"(c[2]), "+f"(c[3])
        : "r"(a[0]), "r"(a[1]), "r"(a[2]), "r"(a[3]), "r"(b[0]), "r"(b[1]));
}

// ---------------- HMMA bf16-split GEMM: C = A * B^T (3 passes) ----------------
// Used for q-proj and out-proj. EPI 0 only: fp32 store.
#define ROWB  80
#define TILEB (128 * ROWB)
#define SMEM_TOT (8 * TILEB)

template <int EPI>
__global__ void __launch_bounds__(256, 2)
mma_gemm(const __nv_bfloat16* __restrict__ Ah, const __nv_bfloat16* __restrict__ Al,
         const __nv_bfloat16* __restrict__ Bh, const __nv_bfloat16* __restrict__ Bl,
         void* __restrict__ C0,
         int K, int lda, int ldb, int ldc)
{
    extern __shared__ char smch[];
    const uint32_t smb = s2u(smch);
    const int tid = threadIdx.x, lane = tid & 31, wid = tid >> 5;
    const int warpM = wid & 1, warpN = wid >> 1;
    const int bm = blockIdx.y * 128, bn = blockIdx.x * 128;

    const __nv_bfloat16* src[4];
    src[0] = Ah + (long long)bm * lda;
    src[1] = Al + (long long)bm * lda;
    src[2] = Bh + (long long)bn * ldb;
    src[3] = Bl + (long long)bn * ldb;

    const int aLR = (lane & 7) + ((lane >> 3) & 1) * 8;
    const int aLK = (lane >> 4) * 8;
    const int bLR = (lane & 7) + (lane >> 4) * 8;
    const int bLK = ((lane >> 3) & 1) * 8;
    int aOff[4], bOff[2];
    #pragma unroll
    for (int m = 0; m < 4; m++) aOff[m] = (warpM * 64 + m * 16 + aLR) * ROWB + aLK * 2;
    #pragma unroll
    for (int p = 0; p < 2; p++) bOff[p] = (warpN * 32 + p * 16 + bLR) * ROWB + bLK * 2;

    float acc[4][4][4] = {};
    const int nCh = K >> 5;

    auto load_stage = [&](int st, int k0) {
        #pragma unroll
        for (int w = 0; w < 4; w++) {
            const __nv_bfloat16* s = src[w] + k0;
            const int ld = (w < 2) ? lda : ldb;
            const uint32_t dst = smb + (uint32_t)(st * 4 + w) * TILEB;
            #pragma unroll
            for (int i = 0; i < 2; i++) {
                const int u = tid + i * 256;
                const int row = u >> 2, c = u & 3;
                cpasync16(dst + row * ROWB + c * 16, s + (long long)row * ld + c * 8);
            }
        }
    };

    load_stage(0, 0);
    asm volatile("cp.async.commit_group;" ::: "memory");

    for (int t = 0; t < nCh; t++) {
        if (t + 1 < nCh) {
            load_stage((t + 1) & 1, (t + 1) * 32);
            asm volatile("cp.async.commit_group;" ::: "memory");
            asm volatile("cp.async.wait_group 1;" ::: "memory");
        } else {
            asm volatile("cp.async.wait_group 0;" ::: "memory");
        }
        __syncthreads();

        const uint32_t base = smb + (uint32_t)((t & 1) * 4) * TILEB;
        #pragma unroll
        for (int kk = 0; kk < 2; kk++) {
            uint32_t bh[8], bl[8];
            #pragma unroll
            for (int p = 0; p < 2; p++) {
                ldsm4(bh + 4 * p, base + 2 * TILEB + bOff[p] + kk * 32);
                ldsm4(bl + 4 * p, base + 3 * TILEB + bOff[p] + kk * 32);
            }
            #pragma unroll
            for (int m = 0; m < 4; m++) {
                uint32_t ah[4], al[4];
                ldsm4(ah, base + 0 * TILEB + aOff[m] + kk * 32);
                ldsm4(al, base + 1 * TILEB + aOff[m] + kk * 32);
                #pragma unroll
                for (int n = 0; n < 4; n++) {
                    mma16816(acc[m][n], ah, bh + 2 * n);
                    mma16816(acc[m][n], ah, bl + 2 * n);
                    mma16816(acc[m][n], al, bh + 2 * n);
                }
            }
        }
        __syncthreads();
    }

    const int qr = lane >> 2, qc = (lane & 3) * 2;
    #pragma unroll
    for (int m = 0; m < 4; m++) {
        const int r0 = bm + warpM * 64 + m * 16 + qr;
        const int r1 = r0 + 8;
        float* C = (float*)C0;
        #pragma unroll
        for (int n = 0; n < 4; n++) {
            const int c = bn + warpN * 32 + n * 8 + qc;
            *reinterpret_cast<float2*>(C + (long long)r0 * ldc + c) =
                make_float2(acc[m][n][0], acc[m][n][1]);
            *reinterpret_cast<float2*>(C + (long long)r1 * ldc + c) =
                make_float2(acc[m][n][2], acc[m][n][3]);
        }
    }
}

// ---------------- fused attention: S = Qn*Kn^T, P = exp(S), y = P*V / rowsum ---
// CTA: 128 q-rows x 1 head, loops over 16 KV tiles of 128 slots.
// Q hi/lo resident in smem; K tile and V^T tile stream via cp.async buffers.
// P never leaves registers: S C-frag -> exp -> bf16 hi/lo A-frag for P*V.
#define PITCH 272                  // 128 bf16 cols * 2B + 16B pad (17x16B, odd -> conflict-free)
#define MATB  (128 * PITCH)        // 34816 B per matrix
#define F_Q   0
#define F_K   (2 * MATB)
#define F_V   (4 * MATB)
#define F_TOT (6 * MATB)           // 208896 B

__global__ void __launch_bounds__(256, 1)
fused_attn(const __nv_bfloat16* __restrict__ qh, const __nv_bfloat16* __restrict__ ql,
           const __nv_bfloat16* __restrict__ kh, const __nv_bfloat16* __restrict__ kl,
           const __nv_bfloat16* __restrict__ vh, const __nv_bfloat16* __restrict__ vl,
           __nv_bfloat16* __restrict__ yh, __nv_bfloat16* __restrict__ yl)
{
    extern __shared__ char smch[];
    const uint32_t smb = s2u(smch);
    const int tid = threadIdx.x, lane = tid & 31, wid = tid >> 5;
    const int bm = blockIdx.x * 128, h = blockIdx.y;

    const int row16 = tid >> 4, c16 = tid & 15;

    // Q tile load (hi/lo)
    #pragma unroll
    for (int i = 0; i < 8; i++) {
        const int r = row16 + i * 16;
        cpasync16(smb + F_Q + r * PITCH + c16 * 16,
                  qh + (size_t)(bm + r) * DM + h * HD + c16 * 8);
        cpasync16(smb + F_Q + MATB + r * PITCH + c16 * 16,
                  ql + (size_t)(bm + r) * DM + h * HD + c16 * 8);
    }
    asm volatile("cp.async.commit_group;" ::: "memory");

    auto load_k = [&](int j) {
        const __nv_bfloat16* sh = kh + ((size_t)h * NK + j * 128) * HD;
        const __nv_bfloat16* sl = kl + ((size_t)h * NK + j * 128) * HD;
        #pragma unroll
        for (int i = 0; i < 8; i++) {
            const int r = row16 + i * 16;           // slot within tile
            cpasync16(smb + F_K + r * PITCH + c16 * 16, sh + (size_t)r * HD + c16 * 8);
            cpasync16(smb + F_K + MATB + r * PITCH + c16 * 16, sl + (size_t)r * HD + c16 * 8);
        }
        asm volatile("cp.async.commit_group;" ::: "memory");
    };
    auto load_v = [&](int j) {
        const __nv_bfloat16* sh = vh + (size_t)h * HD * NK + j * 128;
        const __nv_bfloat16* sl = vl + (size_t)h * HD * NK + j * 128;
        #pragma unroll
        for (int i = 0; i < 8; i++) {
            const int r = row16 + i * 16;           // d index
            cpasync16(smb + F_V + r * PITCH + c16 * 16, sh + (size_t)r * NK + c16 * 8);
            cpasync16(smb + F_V + MATB + r * PITCH + c16 * 16, sl + (size_t)r * NK + c16 * 8);
        }
        asm volatile("cp.async.commit_group;" ::: "memory");
    };

    load_k(0);
    load_v(0);

    const int aLR = (lane & 7) + ((lane >> 3) & 1) * 8;
    const int aLK = (lane >> 4) * 8;
    const int bLR = (lane & 7) + (lane >> 4) * 8;
    const int bLK = ((lane >> 3) & 1) * 8;
    const uint32_t aBase = (uint32_t)(wid * 16 + aLR) * PITCH + aLK * 2;
    const uint32_t bBase = (uint32_t)bLR * PITCH + bLK * 2;

    float accy[16][4] = {};       // y accumulator: 16 rows x 128 d per warp
    float s0 = 0.0f, s1 = 0.0f;   // row sums (rows qr, qr+8)

    for (int j = 0; j < 16; j++) {
        float accs[16][4] = {};   // S tile: 16 rows x 128 slots per warp

        asm volatile("cp.async.wait_group 1;" ::: "memory");   // K_j ready
        __syncthreads();

        // ---- S = Q * K^T (3-pass hi/lo) ----
        #pragma unroll
        for (int t = 0; t < 8; t++) {
            uint32_t ah[4], al[4];
            ldsm4(ah, smb + F_Q + aBase + t * 32);
            ldsm4(al, smb + F_Q + MATB + aBase + t * 32);
            #pragma unroll
            for (int p = 0; p < 8; p++) {
                uint32_t bh[4], bl[4];
                ldsm4(bh, smb + F_K + (uint32_t)p * 16 * PITCH + bBase + t * 32);
                ldsm4(bl, smb + F_K + MATB + (uint32_t)p * 16 * PITCH + bBase + t * 32);
                mma16816(accs[2 * p],     ah, bh);
                mma16816(accs[2 * p + 1], ah, bh + 2);
                mma16816(accs[2 * p],     ah, bl);
                mma16816(accs[2 * p + 1], ah, bl + 2);
                mma16816(accs[2 * p],     al, bh);
                mma16816(accs[2 * p + 1], al, bh + 2);
            }
        }
        __syncthreads();
        if (j + 1 < 16) load_k(j + 1);   // prefetch K over y-phase

        // ---- exp + rowsum (registers only; |S| <= 1 so no max needed) ----
        #pragma unroll
        for (int n = 0; n < 16; n++) {
            accs[n][0] = __expf(accs[n][0]); accs[n][1] = __expf(accs[n][1]);
            accs[n][2] = __expf(accs[n][2]); accs[n][3] = __expf(accs[n][3]);
            s0 += accs[n][0] + accs[n][1];
            s1 += accs[n][2] + accs[n][3];
        }

        asm volatile("cp.async.wait_group 1;" ::: "memory");   // V_j ready
        __syncthreads();

        // ---- y += P * V (3-pass; P frags built in registers) ----
        #pragma unroll
        for (int t = 0; t < 8; t++) {
            uint32_t ph[4], pl[4];
            {
                const float* e0 = accs[2 * t];
                const float* e1 = accs[2 * t + 1];
                float h00 = bfhi(e0[0]), h01 = bfhi(e0[1]), h02 = bfhi(e0[2]), h03 = bfhi(e0[3]);
                float h10 = bfhi(e1[0]), h11 = bfhi(e1[1]), h12 = bfhi(e1[2]), h13 = bfhi(e1[3]);
                ph[0] = packbf2(h00, h01);            ph[1] = packbf2(h02, h03);
                ph[2] = packbf2(h10, h11);            ph[3] = packbf2(h12, h13);
                pl[0] = packbf2(e0[0] - h00, e0[1] - h01);
                pl[1] = packbf2(e0[2] - h02, e0[3] - h03);
                pl[2] = packbf2(e1[0] - h10, e1[1] - h11);
                pl[3] = packbf2(e1[2] - h12, e1[3] - h13);
            }
            #pragma unroll
            for (int p = 0; p < 8; p++) {
                uint32_t bh[4], bl[4];
                ldsm4(bh, smb + F_V + (uint32_t)p * 16 * PITCH + bBase + t * 32);
                ldsm4(bl, smb + F_V + MATB + (uint32_t)p * 16 * PITCH + bBase + t * 32);
                mma16816(accy[2 * p],     ph, bh);
                mma16816(accy[2 * p + 1], ph, bh + 2);
                mma16816(accy[2 * p],     ph, bl);
                mma16816(accy[2 * p + 1], ph, bl + 2);
                mma16816(accy[2 * p],     pl, bh);
                mma16816(accy[2 * p + 1], pl, bh + 2);
            }
        }
        __syncthreads();
        if (j + 1 < 16) load_v(j + 1);   // prefetch V over next S-phase
    }

    // ---- epilogue: divide by rowsum, split to bf16 hi/lo, store ----
    s0 += __shfl_xor_sync(0xffffffffu, s0, 1);
    s0 += __shfl_xor_sync(0xffffffffu, s0, 2);
    s1 += __shfl_xor_sync(0xffffffffu, s1, 1);
    s1 += __shfl_xor_sync(0xffffffffu, s1, 2);
    const float inv0 = 1.0f / s0, inv1 = 1.0f / s1;

    const int qr = lane >> 2, qc = (lane & 3) * 2;
    const int r0 = bm + wid * 16 + qr, r1 = r0 + 8;
    #pragma unroll
    for (int n = 0; n < 16; n++) {
        const int c = h * HD + n * 8 + qc;
        float e0 = accy[n][0] * inv0, e1 = accy[n][1] * inv0;
        float e2 = accy[n][2] * inv1, e3 = accy[n][3] * inv1;
        float h0 = bfhi(e0), h1 = bfhi(e1), h2 = bfhi(e2), h3 = bfhi(e3);
        *reinterpret_cast<uint32_t*>(yh + (size_t)r0 * DM + c) = packbf2(h0, h1);
        *reinterpret_cast<uint32_t*>(yl + (size_t)r0 * DM + c) = packbf2(e0 - h0, e1 - h1);
        *reinterpret_cast<uint32_t*>(yh + (size_t)r1 * DM + c) = packbf2(h2, h3);
        *reinterpret_cast<uint32_t*>(yl + (size_t)r1 * DM + c) = packbf2(e2 - h2, e3 - h3);
    }
}

// ---------------- prep kernels ------------------------------------------------
__global__ void split4_kernel(const float* __restrict__ s, __nv_bfloat16* __restrict__ h,
                              __nv_bfloat16* __restrict__ l, int n4)
{
    const int i = blockIdx.x * 256 + threadIdx.x;
    if (i >= n4) return;
    float4 x = reinterpret_cast<const float4*>(s)[i];
    float ha = bfhi(x.x), hb = bfhi(x.y), hc = bfhi(x.z), hd = bfhi(x.w);
    reinterpret_cast<uint2*>(h)[i] = make_uint2(packbf2(ha, hb), packbf2(hc, hd));
    reinterpret_cast<uint2*>(l)[i] = make_uint2(packbf2(x.x - ha, x.y - hb), packbf2(x.z - hc, x.w - hd));
}

__global__ void transpose_split_kernel(const float* __restrict__ W, __nv_bfloat16* __restrict__ Th,
                                       __nv_bfloat16* __restrict__ Tl, int R, int C)
{
    __shared__ float tile[32][33];
    const int r0 = blockIdx.y * 32, c0 = blockIdx.x * 32;
    for (int i = threadIdx.y; i < 32; i += 8)
        tile[i][threadIdx.x] = W[(long long)(r0 + i) * C + c0 + threadIdx.x];
    __syncthreads();
    for (int i = threadIdx.y; i < 32; i += 8) {
        float x = tile[threadIdx.x][i];
        float hh = bfhi(x);
        long long o = (long long)(c0 + i) * R + r0 + threadIdx.x;
        Th[o] = __float2bfloat16_rn(x);
        Tl[o] = __float2bfloat16_rn(x - hh);
    }
}

__global__ void normalize_q_split_kernel(const float* __restrict__ q,
                                         __nv_bfloat16* __restrict__ qh, __nv_bfloat16* __restrict__ ql)
{
    const int seg = blockIdx.x * 8 + (threadIdx.x >> 5);
    const int lane = threadIdx.x & 31;
    float4 x = reinterpret_cast<const float4*>(q + (size_t)seg * HD)[lane];
    float ss = x.x * x.x + x.y * x.y + x.z * x.z + x.w * x.w;
    #pragma unroll
    for (int o = 16; o > 0; o >>= 1) ss += __shfl_xor_sync(0xffffffffu, ss, o);
    const float rr = rsqrtf(ss + EPSN);
    float a = x.x * rr, b = x.y * rr, cc = x.z * rr, d = x.w * rr;
    float ha = bfhi(a), hb = bfhi(b), hc = bfhi(cc), hd = bfhi(d);
    reinterpret_cast<uint2*>(qh + (size_t)seg * HD)[lane] = make_uint2(packbf2(ha, hb), packbf2(hc, hd));
    reinterpret_cast<uint2*>(ql + (size_t)seg * HD)[lane] =
        make_uint2(packbf2(a - ha, b - hb), packbf2(cc - hc, d - hd));
}

__global__ void prep_k_kernel(const float* __restrict__ keys, const float* __restrict__ scale,
                              __nv_bfloat16* __restrict__ kh, __nv_bfloat16* __restrict__ kl)
{
    const int seg = blockIdx.x * 8 + (threadIdx.x >> 5);
    const int lane = threadIdx.x & 31;
    const int k = seg / NH, h = seg % NH;
    float4 x = reinterpret_cast<const float4*>(keys + (size_t)seg * HD)[lane];
    float ss = x.x * x.x + x.y * x.y + x.z * x.z + x.w * x.w;
    #pragma unroll
    for (int o = 16; o > 0; o >>= 1) ss += __shfl_xor_sync(0xffffffffu, ss, o);
    const float rr = rsqrtf(ss + EPSN) * scale[h];
    float a = x.x * rr, b = x.y * rr, cc = x.z * rr, d = x.w * rr;
    float ha = bfhi(a), hb = bfhi(b), hc = bfhi(cc), hd = bfhi(d);
    const size_t base = ((size_t)h * NK + k) * HD;
    reinterpret_cast<uint2*>(kh + base)[lane] = make_uint2(packbf2(ha, hb), packbf2(hc, hd));
    reinterpret_cast<uint2*>(kl + base)[lane] =
        make_uint2(packbf2(a - ha, b - hb), packbf2(cc - hc, d - hd));
}

__global__ void prep_v_kernel(const float* __restrict__ values,
                              __nv_bfloat16* __restrict__ vh, __nv_bfloat16* __restrict__ vl)
{
    __shared__ float tile[32][33];
    const int h = blockIdx.z, k0 = blockIdx.x * 32, d0 = blockIdx.y * 32;
    for (int i = threadIdx.y; i < 32; i += 8)
        tile[i][threadIdx.x] = values[((size_t)(k0 + i) * NH + h) * HD + d0 + threadIdx.x];
    __syncthreads();
    for (int i = threadIdx.y; i < 32; i += 8) {
        float x = tile[threadIdx.x][i];
        float hh = bfhi(x);
        size_t o = ((size_t)h * HD + d0 + i) * NK + k0 + threadIdx.x;
        vh[o] = __float2bfloat16_rn(x);
        vl[o] = __float2bfloat16_rn(x - hh);
    }
}

// ---------------- launch ------------------------------------------------------
extern "C" void kernel_launch(void* const* d_in, const int* in_sizes, int n_in,
                              void* d_out, int out_size)
{
    const float* x      = (const float*)d_in[0];
    const float* Wq     = (const float*)d_in[1];
    const float* keys   = (const float*)d_in[2];
    const float* values = (const float*)d_in[3];
    const float* scale  = (const float*)d_in[4];
    const float* Wo     = (const float*)d_in[5];
    float* out = (float*)d_out;

    __nv_bfloat16 *pxh, *pxl, *pwqh, *pwql, *pwoh, *pwol, *pqnh, *pqnl;
    __nv_bfloat16 *pkh, *pkl, *pvh, *pvl, *pyh, *pyl;
    float *pq;
    cudaGetSymbolAddress((void**)&pxh, g_xh);   cudaGetSymbolAddress((void**)&pxl, g_xl);
    cudaGetSymbolAddress((void**)&pwqh, g_wqh); cudaGetSymbolAddress((void**)&pwql, g_wql);
    cudaGetSymbolAddress((void**)&pwoh, g_woh); cudaGetSymbolAddress((void**)&pwol, g_wol);
    cudaGetSymbolAddress((void**)&pqnh, g_qnh); cudaGetSymbolAddress((void**)&pqnl, g_qnl);
    cudaGetSymbolAddress((void**)&pkh, g_knh);  cudaGetSymbolAddress((void**)&pkl, g_knl);
    cudaGetSymbolAddress((void**)&pvh, g_vth);  cudaGetSymbolAddress((void**)&pvl, g_vtl);
    cudaGetSymbolAddress((void**)&pyh, g_yh);   cudaGetSymbolAddress((void**)&pyl, g_yl);
    cudaGetSymbolAddress((void**)&pq, g_q);

    cudaFuncSetAttribute(mma_gemm<0>, cudaFuncAttributeMaxDynamicSharedMemorySize, SMEM_TOT);
    cudaFuncSetAttribute(fused_attn, cudaFuncAttributeMaxDynamicSharedMemorySize, F_TOT);

    // prep: splits and transposes
    split4_kernel<<<(S_LEN * DM / 4 + 255) / 256, 256>>>(x, pxh, pxl, S_LEN * DM / 4);
    transpose_split_kernel<<<dim3(DM / 32, DM / 32), dim3(32, 8)>>>(Wq, pwqh, pwql, DM, DM);
    transpose_split_kernel<<<dim3(DM / 32, DM / 32), dim3(32, 8)>>>(Wo, pwoh, pwol, DM, DM);
    prep_k_kernel<<<(NK * NH) / 8, 256>>>(keys, scale, pkh, pkl);
    prep_v_kernel<<<dim3(NK / 32, HD / 32, NH), dim3(32, 8)>>>(values, pvh, pvl);

    // 1) q = x @ Wq  (fp32 out)
    mma_gemm<0><<<dim3(DM / 128, S_LEN / 128, 1), 256, SMEM_TOT>>>(
        pxh, pxl, pwqh, pwql, pq, DM, DM, DM, DM);

    // 2) normalize q, split to bf16
    normalize_q_split_kernel<<<(S_LEN * NH) / 8, 256>>>(pq, pqnh, pqnl);

    // 3) fused attention: scores + softmax + P@V, y in bf16 hi/lo merged layout
    fused_attn<<<dim3(S_LEN / 128, NH), 256, F_TOT>>>(
        pqnh, pqnl, pkh, pkl, pvh, pvl, pyh, pyl);

    // 4) out = y @ Wo  (fp32 out)
    mma_gemm<0><<<dim3(DM / 128, S_LEN / 128, 1), 256, SMEM_TOT>>>(
        pyh, pyl, pwoh, pwol, out, DM, DM, DM, DM);
}

// round 11
// speedup vs baseline: 4.3835x; 1.3266x over previous
#include <cuda_runtime.h>
#include <cuda_bf16.h>
#include <cuda_fp16.h>
#include <cstdint>
#include <math.h>

#define S_LEN 4096
#define DM    1024
#define NH    8
#define HD    128
#define NK    2048
#define EPSN  1e-6f

// ---------------- scratch (device globals; no allocation allowed) -------------
__device__ __nv_bfloat16 g_xh[(size_t)S_LEN * DM], g_xl[(size_t)S_LEN * DM];
__device__ __nv_bfloat16 g_wqh[(size_t)DM * DM],   g_wql[(size_t)DM * DM];
__device__ __nv_bfloat16 g_woh[(size_t)DM * DM],   g_wol[(size_t)DM * DM];
__device__ __half        g_qn[(size_t)S_LEN * DM];          // normalized q, fp16
__device__ __half        g_kh[(size_t)NH * NK * HD];        // normalized*scaled K, fp16
__device__ __half        g_vh[(size_t)NH * HD * NK];        // V^T hi, fp16
__device__ __half        g_vl[(size_t)NH * HD * NK];        // V^T lo, fp16
__device__ __nv_bfloat16 g_yh[(size_t)S_LEN * DM], g_yl[(size_t)S_LEN * DM];

// ---------------- helpers -----------------------------------------------------
__device__ __forceinline__ uint32_t s2u(const void* p) {
    uint32_t a;
    asm("{ .reg .u64 t; cvta.to.shared.u64 t, %1; cvt.u32.u64 %0, t; }" : "=r"(a) : "l"(p));
    return a;
}
__device__ __forceinline__ float bfhi(float x) { return __bfloat162float(__float2bfloat16_rn(x)); }
__device__ __forceinline__ uint32_t packbf2(float a, float b) {
    __nv_bfloat162 t = __floats2bfloat162_rn(a, b);
    return reinterpret_cast<uint32_t&>(t);
}
__device__ __forceinline__ uint32_t packh2(float a, float b) {
    __half2 t = __floats2half2_rn(a, b);
    return reinterpret_cast<uint32_t&>(t);
}
__device__ __forceinline__ void cpasync16(uint32_t dst, const void* src) {
    asm volatile("cp.async.cg.shared.global [%0], [%1], 16;" :: "r"(dst), "l"(src));
}
__device__ __forceinline__ void ldsm4(uint32_t* r, uint32_t addr) {
    asm volatile("ldmatrix.sync.aligned.m8n8.x4.shared.b16 {%0,%1,%2,%3}, [%4];"
        : "=r"(r[0]), "=r"(r[1]), "=r"(r[2]), "=r"(r[3]) : "r"(addr));
}
__device__ __forceinline__ void mma16816(float* c, const uint32_t* a, const uint32_t* b) {
    asm volatile("mma.sync.aligned.m16n8k16.row.col.f32.bf16.bf16.f32 "
        "{%0,%1,%2,%3}, {%4,%5,%6,%7}, {%8,%9}, {%0,%1,%2,%3};"
        : "+f"(c[0]), "+f"(c[1]), "+f"(c[2]), "+f"(c[3])
        : "r"(a[0]), "r"(a[1]), "r"(a[2]), "r"(a[3]), "r"(b[0]), "r"(b[1]));
}
__device__ __forceinline__ void mma_h(float* c, const uint32_t* a, const uint32_t* b) {
    asm volatile("mma.sync.aligned.m16n8k16.row.col.f32.f16.f16.f32 "
        "{%0,%1,%2,%3}, {%4,%5,%6,%7}, {%8,%9}, {%0,%1,%2,%3};"
        : "+f"(c[0]), "+f"(c[1]), "+f"(c[2]), "+f"(c[3])
        : "r"(a[0]), "r"(a[1]), "r"(a[2]), "r"(a[3]), "r"(b[0]), "r"(b[1]));
}

// ---------------- HMMA bf16-split GEMM: C = A * B^T (3 passes) ----------------
// EPI 0: fp32 store. EPI 3: per-row L2-normalize over the 128-col tile (= one
// head segment) and store fp16 (for q-projection).
#define ROWB  80
#define TILEB (128 * ROWB)
#define SMEM_TOT (8 * TILEB)

template <int EPI>
__global__ void __launch_bounds__(256, 2)
mma_gemm(const __nv_bfloat16* __restrict__ Ah, const __nv_bfloat16* __restrict__ Al,
         const __nv_bfloat16* __restrict__ Bh, const __nv_bfloat16* __restrict__ Bl,
         void* __restrict__ C0,
         int K, int lda, int ldb, int ldc)
{
    extern __shared__ char smch[];
    const uint32_t smb = s2u(smch);
    const int tid = threadIdx.x, lane = tid & 31, wid = tid >> 5;
    const int warpM = wid & 1, warpN = wid >> 1;
    const int bm = blockIdx.y * 128, bn = blockIdx.x * 128;

    const __nv_bfloat16* src[4];
    src[0] = Ah + (long long)bm * lda;
    src[1] = Al + (long long)bm * lda;
    src[2] = Bh + (long long)bn * ldb;
    src[3] = Bl + (long long)bn * ldb;

    const int aLR = (lane & 7) + ((lane >> 3) & 1) * 8;
    const int aLK = (lane >> 4) * 8;
    const int bLR = (lane & 7) + (lane >> 4) * 8;
    const int bLK = ((lane >> 3) & 1) * 8;
    int aOff[4], bOff[2];
    #pragma unroll
    for (int m = 0; m < 4; m++) aOff[m] = (warpM * 64 + m * 16 + aLR) * ROWB + aLK * 2;
    #pragma unroll
    for (int p = 0; p < 2; p++) bOff[p] = (warpN * 32 + p * 16 + bLR) * ROWB + bLK * 2;

    float acc[4][4][4] = {};
    const int nCh = K >> 5;

    auto load_stage = [&](int st, int k0) {
        #pragma unroll
        for (int w = 0; w < 4; w++) {
            const __nv_bfloat16* s = src[w] + k0;
            const int ld = (w < 2) ? lda : ldb;
            const uint32_t dst = smb + (uint32_t)(st * 4 + w) * TILEB;
            #pragma unroll
            for (int i = 0; i < 2; i++) {
                const int u = tid + i * 256;
                const int row = u >> 2, c = u & 3;
                cpasync16(dst + row * ROWB + c * 16, s + (long long)row * ld + c * 8);
            }
        }
    };

    load_stage(0, 0);
    asm volatile("cp.async.commit_group;" ::: "memory");

    for (int t = 0; t < nCh; t++) {
        if (t + 1 < nCh) {
            load_stage((t + 1) & 1, (t + 1) * 32);
            asm volatile("cp.async.commit_group;" ::: "memory");
            asm volatile("cp.async.wait_group 1;" ::: "memory");
        } else {
            asm volatile("cp.async.wait_group 0;" ::: "memory");
        }
        __syncthreads();

        const uint32_t base = smb + (uint32_t)((t & 1) * 4) * TILEB;
        #pragma unroll
        for (int kk = 0; kk < 2; kk++) {
            uint32_t bh[8], bl[8];
            #pragma unroll
            for (int p = 0; p < 2; p++) {
                ldsm4(bh + 4 * p, base + 2 * TILEB + bOff[p] + kk * 32);
                ldsm4(bl + 4 * p, base + 3 * TILEB + bOff[p] + kk * 32);
            }
            #pragma unroll
            for (int m = 0; m < 4; m++) {
                uint32_t ah[4], al[4];
                ldsm4(ah, base + 0 * TILEB + aOff[m] + kk * 32);
                ldsm4(al, base + 1 * TILEB + aOff[m] + kk * 32);
                #pragma unroll
                for (int n = 0; n < 4; n++) {
                    mma16816(acc[m][n], ah, bh + 2 * n);
                    mma16816(acc[m][n], ah, bl + 2 * n);
                    mma16816(acc[m][n], al, bh + 2 * n);
                }
            }
        }
        __syncthreads();
    }

    const int qr = lane >> 2, qc = (lane & 3) * 2;

    if (EPI == 0) {
        #pragma unroll
        for (int m = 0; m < 4; m++) {
            const int r0 = bm + warpM * 64 + m * 16 + qr;
            const int r1 = r0 + 8;
            float* C = (float*)C0;
            #pragma unroll
            for (int n = 0; n < 4; n++) {
                const int c = bn + warpN * 32 + n * 8 + qc;
                *reinterpret_cast<float2*>(C + (long long)r0 * ldc + c) =
                    make_float2(acc[m][n][0], acc[m][n][1]);
                *reinterpret_cast<float2*>(C + (long long)r1 * ldc + c) =
                    make_float2(acc[m][n][2], acc[m][n][3]);
            }
        }
    } else {
        // EPI 3: row L2-normalize across the 128-col tile, write fp16
        float* ssm = (float*)smch;              // 128 per-row sums (tile-local)
        if (tid < 128) ssm[tid] = 0.0f;
        __syncthreads();
        #pragma unroll
        for (int m = 0; m < 4; m++) {
            float p0 = 0.0f, p1 = 0.0f;
            #pragma unroll
            for (int n = 0; n < 4; n++) {
                p0 += acc[m][n][0] * acc[m][n][0] + acc[m][n][1] * acc[m][n][1];
                p1 += acc[m][n][2] * acc[m][n][2] + acc[m][n][3] * acc[m][n][3];
            }
            p0 += __shfl_xor_sync(0xffffffffu, p0, 1);
            p0 += __shfl_xor_sync(0xffffffffu, p0, 2);
            p1 += __shfl_xor_sync(0xffffffffu, p1, 1);
            p1 += __shfl_xor_sync(0xffffffffu, p1, 2);
            if ((lane & 3) == 0) {
                atomicAdd(ssm + warpM * 64 + m * 16 + qr, p0);
                atomicAdd(ssm + warpM * 64 + m * 16 + qr + 8, p1);
            }
        }
        __syncthreads();
        __half* Q = (__half*)C0;
        #pragma unroll
        for (int m = 0; m < 4; m++) {
            const int lr0 = warpM * 64 + m * 16 + qr, lr1 = lr0 + 8;
            const float i0 = rsqrtf(ssm[lr0] + EPSN);
            const float i1 = rsqrtf(ssm[lr1] + EPSN);
            const int r0 = bm + lr0, r1 = bm + lr1;
            #pragma unroll
            for (int n = 0; n < 4; n++) {
                const int c = bn + warpN * 32 + n * 8 + qc;
                *reinterpret_cast<uint32_t*>(Q + (long long)r0 * ldc + c) =
                    packh2(acc[m][n][0] * i0, acc[m][n][1] * i0);
                *reinterpret_cast<uint32_t*>(Q + (long long)r1 * ldc + c) =
                    packh2(acc[m][n][2] * i1, acc[m][n][3] * i1);
            }
        }
    }
}

// ---------------- fused attention (fp16): S=Q*K^T 1-pass, y=P*V 2-pass --------
// CTA: 128 q-rows x 1 head, 16 KV tiles of 128 slots. Q,K single fp16; V fp16
// hi/lo. P stays in registers (C-frag -> exp -> fp16 A-frag).
#define PITCH 272
#define MATB  (128 * PITCH)        // 34816 B
#define FA_Q  0
#define FA_K  MATB
#define FA_VH (2 * MATB)
#define FA_VL (3 * MATB)
#define FA_TOT (4 * MATB)          // 139264 B

__global__ void __launch_bounds__(256, 1)
fused_attn(const __half* __restrict__ qn, const __half* __restrict__ kh,
           const __half* __restrict__ vh, const __half* __restrict__ vl,
           __nv_bfloat16* __restrict__ yh, __nv_bfloat16* __restrict__ yl)
{
    extern __shared__ char smch[];
    const uint32_t smb = s2u(smch);
    const int tid = threadIdx.x, lane = tid & 31, wid = tid >> 5;
    const int bm = blockIdx.x * 128, h = blockIdx.y;
    const int row16 = tid >> 4, c16 = tid & 15;

    // Q tile (fp16 single): 128 rows x 256 B
    #pragma unroll
    for (int i = 0; i < 8; i++) {
        const int r = row16 + i * 16;
        cpasync16(smb + FA_Q + r * PITCH + c16 * 16,
                  qn + (size_t)(bm + r) * DM + h * HD + c16 * 8);
    }
    asm volatile("cp.async.commit_group;" ::: "memory");

    auto load_k = [&](int j) {
        const __half* s = kh + ((size_t)h * NK + j * 128) * HD;
        #pragma unroll
        for (int i = 0; i < 8; i++) {
            const int r = row16 + i * 16;
            cpasync16(smb + FA_K + r * PITCH + c16 * 16, s + (size_t)r * HD + c16 * 8);
        }
        asm volatile("cp.async.commit_group;" ::: "memory");
    };
    auto load_v = [&](int j) {
        const __half* sh = vh + (size_t)h * HD * NK + j * 128;
        const __half* sl = vl + (size_t)h * HD * NK + j * 128;
        #pragma unroll
        for (int i = 0; i < 8; i++) {
            const int r = row16 + i * 16;           // d index
            cpasync16(smb + FA_VH + r * PITCH + c16 * 16, sh + (size_t)r * NK + c16 * 8);
            cpasync16(smb + FA_VL + r * PITCH + c16 * 16, sl + (size_t)r * NK + c16 * 8);
        }
        asm volatile("cp.async.commit_group;" ::: "memory");
    };

    load_k(0);
    load_v(0);

    const int aLR = (lane & 7) + ((lane >> 3) & 1) * 8;
    const int aLK = (lane >> 4) * 8;
    const int bLR = (lane & 7) + (lane >> 4) * 8;
    const int bLK = ((lane >> 3) & 1) * 8;
    const uint32_t aBase = (uint32_t)(wid * 16 + aLR) * PITCH + aLK * 2;
    const uint32_t bBase = (uint32_t)bLR * PITCH + bLK * 2;

    float accy[16][4] = {};
    float s0 = 0.0f, s1 = 0.0f;

    for (int j = 0; j < 16; j++) {
        float accs[16][4] = {};

        asm volatile("cp.async.wait_group 1;" ::: "memory");   // K_j ready
        __syncthreads();

        // ---- S = Q * K^T (fp16, single pass) ----
        #pragma unroll
        for (int t = 0; t < 8; t++) {
            uint32_t a[4];
            ldsm4(a, smb + FA_Q + aBase + t * 32);
            #pragma unroll
            for (int p = 0; p < 8; p++) {
                uint32_t b[4];
                ldsm4(b, smb + FA_K + (uint32_t)p * 16 * PITCH + bBase + t * 32);
                mma_h(accs[2 * p],     a, b);
                mma_h(accs[2 * p + 1], a, b + 2);
            }
        }
        __syncthreads();
        if (j + 1 < 16) load_k(j + 1);

        // ---- exp + rowsum (|S| <= 1, no max shift needed) ----
        #pragma unroll
        for (int n = 0; n < 16; n++) {
            accs[n][0] = __expf(accs[n][0]); accs[n][1] = __expf(accs[n][1]);
            accs[n][2] = __expf(accs[n][2]); accs[n][3] = __expf(accs[n][3]);
            s0 += accs[n][0] + accs[n][1];
            s1 += accs[n][2] + accs[n][3];
        }

        asm volatile("cp.async.wait_group 1;" ::: "memory");   // V_j ready
        __syncthreads();

        // ---- y += P * (Vh + Vl)  (P single fp16, V split fp16: 2 passes) ----
        #pragma unroll
        for (int t = 0; t < 8; t++) {
            uint32_t pf[4];
            {
                const float* e0 = accs[2 * t];
                const float* e1 = accs[2 * t + 1];
                pf[0] = packh2(e0[0], e0[1]);
                pf[1] = packh2(e0[2], e0[3]);
                pf[2] = packh2(e1[0], e1[1]);
                pf[3] = packh2(e1[2], e1[3]);
            }
            #pragma unroll
            for (int p = 0; p < 8; p++) {
                uint32_t bh[4], bl[4];
                ldsm4(bh, smb + FA_VH + (uint32_t)p * 16 * PITCH + bBase + t * 32);
                ldsm4(bl, smb + FA_VL + (uint32_t)p * 16 * PITCH + bBase + t * 32);
                mma_h(accy[2 * p],     pf, bh);
                mma_h(accy[2 * p + 1], pf, bh + 2);
                mma_h(accy[2 * p],     pf, bl);
                mma_h(accy[2 * p + 1], pf, bl + 2);
            }
        }
        __syncthreads();
        if (j + 1 < 16) load_v(j + 1);
    }

    // ---- epilogue: /rowsum, bf16 hi/lo split, store ----
    s0 += __shfl_xor_sync(0xffffffffu, s0, 1);
    s0 += __shfl_xor_sync(0xffffffffu, s0, 2);
    s1 += __shfl_xor_sync(0xffffffffu, s1, 1);
    s1 += __shfl_xor_sync(0xffffffffu, s1, 2);
    const float inv0 = 1.0f / s0, inv1 = 1.0f / s1;

    const int qr = lane >> 2, qc = (lane & 3) * 2;
    const int r0 = bm + wid * 16 + qr, r1 = r0 + 8;
    #pragma unroll
    for (int n = 0; n < 16; n++) {
        const int c = h * HD + n * 8 + qc;
        float e0 = accy[n][0] * inv0, e1 = accy[n][1] * inv0;
        float e2 = accy[n][2] * inv1, e3 = accy[n][3] * inv1;
        float h0 = bfhi(e0), h1 = bfhi(e1), h2 = bfhi(e2), h3 = bfhi(e3);
        *reinterpret_cast<uint32_t*>(yh + (size_t)r0 * DM + c) = packbf2(h0, h1);
        *reinterpret_cast<uint32_t*>(yl + (size_t)r0 * DM + c) = packbf2(e0 - h0, e1 - h1);
        *reinterpret_cast<uint32_t*>(yh + (size_t)r1 * DM + c) = packbf2(h2, h3);
        *reinterpret_cast<uint32_t*>(yl + (size_t)r1 * DM + c) = packbf2(e2 - h2, e3 - h3);
    }
}

// ---------------- prep kernels ------------------------------------------------
__global__ void split4_kernel(const float* __restrict__ s, __nv_bfloat16* __restrict__ h,
                              __nv_bfloat16* __restrict__ l, int n4)
{
    const int i = blockIdx.x * 256 + threadIdx.x;
    if (i >= n4) return;
    float4 x = reinterpret_cast<const float4*>(s)[i];
    float ha = bfhi(x.x), hb = bfhi(x.y), hc = bfhi(x.z), hd = bfhi(x.w);
    reinterpret_cast<uint2*>(h)[i] = make_uint2(packbf2(ha, hb), packbf2(hc, hd));
    reinterpret_cast<uint2*>(l)[i] = make_uint2(packbf2(x.x - ha, x.y - hb), packbf2(x.z - hc, x.w - hd));
}

__global__ void transpose_split_kernel(const float* __restrict__ W, __nv_bfloat16* __restrict__ Th,
                                       __nv_bfloat16* __restrict__ Tl, int R, int C)
{
    __shared__ float tile[32][33];
    const int r0 = blockIdx.y * 32, c0 = blockIdx.x * 32;
    for (int i = threadIdx.y; i < 32; i += 8)
        tile[i][threadIdx.x] = W[(long long)(r0 + i) * C + c0 + threadIdx.x];
    __syncthreads();
    for (int i = threadIdx.y; i < 32; i += 8) {
        float x = tile[threadIdx.x][i];
        float hh = bfhi(x);
        long long o = (long long)(c0 + i) * R + r0 + threadIdx.x;
        Th[o] = __float2bfloat16_rn(x);
        Tl[o] = __float2bfloat16_rn(x - hh);
    }
}

// keys: row n = k*NH+h -> normalized*scale, fp16 single, layout [h][k][d]
__global__ void prep_k_kernel(const float* __restrict__ keys, const float* __restrict__ scale,
                              __half* __restrict__ kout)
{
    const int seg = blockIdx.x * 8 + (threadIdx.x >> 5);
    const int lane = threadIdx.x & 31;
    const int k = seg / NH, h = seg % NH;
    float4 x = reinterpret_cast<const float4*>(keys + (size_t)seg * HD)[lane];
    float ss = x.x * x.x + x.y * x.y + x.z * x.z + x.w * x.w;
    #pragma unroll
    for (int o = 16; o > 0; o >>= 1) ss += __shfl_xor_sync(0xffffffffu, ss, o);
    const float rr = rsqrtf(ss + EPSN) * scale[h];
    const size_t base = ((size_t)h * NK + k) * HD;
    reinterpret_cast<uint2*>(kout + base)[lane] =
        make_uint2(packh2(x.x * rr, x.y * rr), packh2(x.z * rr, x.w * rr));
}

// values: [k][h][d] -> vT[h][d][k], fp16 hi/lo split
__global__ void prep_v_kernel(const float* __restrict__ values,
                              __half* __restrict__ vh, __half* __restrict__ vl)
{
    __shared__ float tile[32][33];
    const int h = blockIdx.z, k0 = blockIdx.x * 32, d0 = blockIdx.y * 32;
    for (int i = threadIdx.y; i < 32; i += 8)
        tile[i][threadIdx.x] = values[((size_t)(k0 + i) * NH + h) * HD + d0 + threadIdx.x];
    __syncthreads();
    for (int i = threadIdx.y; i < 32; i += 8) {
        float x = tile[threadIdx.x][i];
        __half hx = __float2half_rn(x);
        size_t o = ((size_t)h * HD + d0 + i) * NK + k0 + threadIdx.x;
        vh[o] = hx;
        vl[o] = __float2half_rn(x - __half2float(hx));
    }
}

// ---------------- launch ------------------------------------------------------
extern "C" void kernel_launch(void* const* d_in, const int* in_sizes, int n_in,
                              void* d_out, int out_size)
{
    const float* x      = (const float*)d_in[0];
    const float* Wq     = (const float*)d_in[1];
    const float* keys   = (const float*)d_in[2];
    const float* values = (const float*)d_in[3];
    const float* scale  = (const float*)d_in[4];
    const float* Wo     = (const float*)d_in[5];
    float* out = (float*)d_out;

    __nv_bfloat16 *pxh, *pxl, *pwqh, *pwql, *pwoh, *pwol, *pyh, *pyl;
    __half *pqn, *pkh, *pvh, *pvl;
    cudaGetSymbolAddress((void**)&pxh, g_xh);   cudaGetSymbolAddress((void**)&pxl, g_xl);
    cudaGetSymbolAddress((void**)&pwqh, g_wqh); cudaGetSymbolAddress((void**)&pwql, g_wql);
    cudaGetSymbolAddress((void**)&pwoh, g_woh); cudaGetSymbolAddress((void**)&pwol, g_wol);
    cudaGetSymbolAddress((void**)&pqn, g_qn);
    cudaGetSymbolAddress((void**)&pkh, g_kh);
    cudaGetSymbolAddress((void**)&pvh, g_vh);   cudaGetSymbolAddress((void**)&pvl, g_vl);
    cudaGetSymbolAddress((void**)&pyh, g_yh);   cudaGetSymbolAddress((void**)&pyl, g_yl);

    cudaFuncSetAttribute(mma_gemm<0>, cudaFuncAttributeMaxDynamicSharedMemorySize, SMEM_TOT);
    cudaFuncSetAttribute(mma_gemm<3>, cudaFuncAttributeMaxDynamicSharedMemorySize, SMEM_TOT);
    cudaFuncSetAttribute(fused_attn, cudaFuncAttributeMaxDynamicSharedMemorySize, FA_TOT);

    // prep
    split4_kernel<<<(S_LEN * DM / 4 + 255) / 256, 256>>>(x, pxh, pxl, S_LEN * DM / 4);
    transpose_split_kernel<<<dim3(DM / 32, DM / 32), dim3(32, 8)>>>(Wq, pwqh, pwql, DM, DM);
    transpose_split_kernel<<<dim3(DM / 32, DM / 32), dim3(32, 8)>>>(Wo, pwoh, pwol, DM, DM);
    prep_k_kernel<<<(NK * NH) / 8, 256>>>(keys, scale, pkh);
    prep_v_kernel<<<dim3(NK / 32, HD / 32, NH), dim3(32, 8)>>>(values, pvh, pvl);

    // 1) q = normalize(x @ Wq) -> fp16 (normalization fused into epilogue)
    mma_gemm<3><<<dim3(DM / 128, S_LEN / 128, 1), 256, SMEM_TOT>>>(
        pxh, pxl, pwqh, pwql, pqn, DM, DM, DM, DM);

    // 2) fused attention (fp16): scores + softmax + P@V -> y bf16 hi/lo
    fused_attn<<<dim3(S_LEN / 128, NH), 256, FA_TOT>>>(
        pqn, pkh, pvh, pvl, pyh, pyl);

    // 3) out = y @ Wo (bf16 3-pass, fp32 out)
    mma_gemm<0><<<dim3(DM / 128, S_LEN / 128, 1), 256, SMEM_TOT>>>(
        pyh, pyl, pwoh, pwol, out, DM, DM, DM, DM);
}

// round 12
// speedup vs baseline: 5.0257x; 1.1465x over previous
#include <cuda_runtime.h>
#include <cuda_bf16.h>
#include <cuda_fp16.h>
#include <cstdint>
#include <math.h>

#define S_LEN 4096
#define DM    1024
#define NH    8
#define HD    128
#define NK    2048
#define EPSN  1e-6f

// ---------------- scratch (device globals; no allocation allowed) -------------
__device__ __nv_bfloat16 g_xh[(size_t)S_LEN * DM], g_xl[(size_t)S_LEN * DM];
__device__ __nv_bfloat16 g_wqh[(size_t)DM * DM],   g_wql[(size_t)DM * DM];
__device__ __nv_bfloat16 g_woh[(size_t)DM * DM],   g_wol[(size_t)DM * DM];
__device__ __half        g_qn[(size_t)S_LEN * DM];          // normalized q, fp16
__device__ __half        g_kh[(size_t)NH * NK * HD];        // normalized*scaled K, fp16
__device__ __half        g_vh[(size_t)NH * HD * NK];        // V^T, fp16 single
__device__ __nv_bfloat16 g_yh[(size_t)S_LEN * DM], g_yl[(size_t)S_LEN * DM];

// ---------------- helpers -----------------------------------------------------
__device__ __forceinline__ uint32_t s2u(const void* p) {
    uint32_t a;
    asm("{ .reg .u64 t; cvta.to.shared.u64 t, %1; cvt.u32.u64 %0, t; }" : "=r"(a) : "l"(p));
    return a;
}
__device__ __forceinline__ float bfhi(float x) { return __bfloat162float(__float2bfloat16_rn(x)); }
__device__ __forceinline__ uint32_t packbf2(float a, float b) {
    __nv_bfloat162 t = __floats2bfloat162_rn(a, b);
    return reinterpret_cast<uint32_t&>(t);
}
__device__ __forceinline__ uint32_t packh2(float a, float b) {
    __half2 t = __floats2half2_rn(a, b);
    return reinterpret_cast<uint32_t&>(t);
}
__device__ __forceinline__ void cpasync16(uint32_t dst, const void* src) {
    asm volatile("cp.async.cg.shared.global [%0], [%1], 16;" :: "r"(dst), "l"(src));
}
__device__ __forceinline__ void ldsm4(uint32_t* r, uint32_t addr) {
    asm volatile("ldmatrix.sync.aligned.m8n8.x4.shared.b16 {%0,%1,%2,%3}, [%4];"
        : "=r"(r[0]), "=r"(r[1]), "=r"(r[2]), "=r"(r[3]) : "r"(addr));
}
__device__ __forceinline__ void mma16816(float* c, const uint32_t* a, const uint32_t* b) {
    asm volatile("mma.sync.aligned.m16n8k16.row.col.f32.bf16.bf16.f32 "
        "{%0,%1,%2,%3}, {%4,%5,%6,%7}, {%8,%9}, {%0,%1,%2,%3};"
        : "+f"(c[0]), "+f"(c[1]), "+f"(c[2]), "+f"(c[3])
        : "r"(a[0]), "r"(a[1]), "r"(a[2]), "r"(a[3]), "r"(b[0]), "r"(b[1]));
}
__device__ __forceinline__ void mma_h(float* c, const uint32_t* a, const uint32_t* b) {
    asm volatile("mma.sync.aligned.m16n8k16.row.col.f32.f16.f16.f32 "
        "{%0,%1,%2,%3}, {%4,%5,%6,%7}, {%8,%9}, {%0,%1,%2,%3};"
        : "+f"(c[0]), "+f"(c[1]), "+f"(c[2]), "+f"(c[3])
        : "r"(a[0]), "r"(a[1]), "r"(a[2]), "r"(a[3]), "r"(b[0]), "r"(b[1]));
}

// ---------------- HMMA bf16-split GEMM: C = A * B^T (3 passes) ----------------
// EPI 0: fp32 store. EPI 3: per-row L2-normalize over the 128-col tile (= one
// head segment) and store fp16 (for q-projection).
#define ROWB  80
#define TILEB (128 * ROWB)
#define SMEM_TOT (8 * TILEB)

template <int EPI>
__global__ void __launch_bounds__(256, 2)
mma_gemm(const __nv_bfloat16* __restrict__ Ah, const __nv_bfloat16* __restrict__ Al,
         const __nv_bfloat16* __restrict__ Bh, const __nv_bfloat16* __restrict__ Bl,
         void* __restrict__ C0,
         int K, int lda, int ldb, int ldc)
{
    extern __shared__ char smch[];
    const uint32_t smb = s2u(smch);
    const int tid = threadIdx.x, lane = tid & 31, wid = tid >> 5;
    const int warpM = wid & 1, warpN = wid >> 1;
    const int bm = blockIdx.y * 128, bn = blockIdx.x * 128;

    const __nv_bfloat16* src[4];
    src[0] = Ah + (long long)bm * lda;
    src[1] = Al + (long long)bm * lda;
    src[2] = Bh + (long long)bn * ldb;
    src[3] = Bl + (long long)bn * ldb;

    const int aLR = (lane & 7) + ((lane >> 3) & 1) * 8;
    const int aLK = (lane >> 4) * 8;
    const int bLR = (lane & 7) + (lane >> 4) * 8;
    const int bLK = ((lane >> 3) & 1) * 8;
    int aOff[4], bOff[2];
    #pragma unroll
    for (int m = 0; m < 4; m++) aOff[m] = (warpM * 64 + m * 16 + aLR) * ROWB + aLK * 2;
    #pragma unroll
    for (int p = 0; p < 2; p++) bOff[p] = (warpN * 32 + p * 16 + bLR) * ROWB + bLK * 2;

    float acc[4][4][4] = {};
    const int nCh = K >> 5;

    auto load_stage = [&](int st, int k0) {
        #pragma unroll
        for (int w = 0; w < 4; w++) {
            const __nv_bfloat16* s = src[w] + k0;
            const int ld = (w < 2) ? lda : ldb;
            const uint32_t dst = smb + (uint32_t)(st * 4 + w) * TILEB;
            #pragma unroll
            for (int i = 0; i < 2; i++) {
                const int u = tid + i * 256;
                const int row = u >> 2, c = u & 3;
                cpasync16(dst + row * ROWB + c * 16, s + (long long)row * ld + c * 8);
            }
        }
    };

    load_stage(0, 0);
    asm volatile("cp.async.commit_group;" ::: "memory");

    for (int t = 0; t < nCh; t++) {
        if (t + 1 < nCh) {
            load_stage((t + 1) & 1, (t + 1) * 32);
            asm volatile("cp.async.commit_group;" ::: "memory");
            asm volatile("cp.async.wait_group 1;" ::: "memory");
        } else {
            asm volatile("cp.async.wait_group 0;" ::: "memory");
        }
        __syncthreads();

        const uint32_t base = smb + (uint32_t)((t & 1) * 4) * TILEB;
        #pragma unroll
        for (int kk = 0; kk < 2; kk++) {
            uint32_t bh[8], bl[8];
            #pragma unroll
            for (int p = 0; p < 2; p++) {
                ldsm4(bh + 4 * p, base + 2 * TILEB + bOff[p] + kk * 32);
                ldsm4(bl + 4 * p, base + 3 * TILEB + bOff[p] + kk * 32);
            }
            #pragma unroll
            for (int m = 0; m < 4; m++) {
                uint32_t ah[4], al[4];
                ldsm4(ah, base + 0 * TILEB + aOff[m] + kk * 32);
                ldsm4(al, base + 1 * TILEB + aOff[m] + kk * 32);
                #pragma unroll
                for (int n = 0; n < 4; n++) {
                    mma16816(acc[m][n], ah, bh + 2 * n);
                    mma16816(acc[m][n], ah, bl + 2 * n);
                    mma16816(acc[m][n], al, bh + 2 * n);
                }
            }
        }
        __syncthreads();
    }

    const int qr = lane >> 2, qc = (lane & 3) * 2;

    if (EPI == 0) {
        #pragma unroll
        for (int m = 0; m < 4; m++) {
            const int r0 = bm + warpM * 64 + m * 16 + qr;
            const int r1 = r0 + 8;
            float* C = (float*)C0;
            #pragma unroll
            for (int n = 0; n < 4; n++) {
                const int c = bn + warpN * 32 + n * 8 + qc;
                *reinterpret_cast<float2*>(C + (long long)r0 * ldc + c) =
                    make_float2(acc[m][n][0], acc[m][n][1]);
                *reinterpret_cast<float2*>(C + (long long)r1 * ldc + c) =
                    make_float2(acc[m][n][2], acc[m][n][3]);
            }
        }
    } else {
        // EPI 3: row L2-normalize across the 128-col tile, write fp16
        float* ssm = (float*)smch;              // 128 per-row sums (tile-local)
        if (tid < 128) ssm[tid] = 0.0f;
        __syncthreads();
        #pragma unroll
        for (int m = 0; m < 4; m++) {
            float p0 = 0.0f, p1 = 0.0f;
            #pragma unroll
            for (int n = 0; n < 4; n++) {
                p0 += acc[m][n][0] * acc[m][n][0] + acc[m][n][1] * acc[m][n][1];
                p1 += acc[m][n][2] * acc[m][n][2] + acc[m][n][3] * acc[m][n][3];
            }
            p0 += __shfl_xor_sync(0xffffffffu, p0, 1);
            p0 += __shfl_xor_sync(0xffffffffu, p0, 2);
            p1 += __shfl_xor_sync(0xffffffffu, p1, 1);
            p1 += __shfl_xor_sync(0xffffffffu, p1, 2);
            if ((lane & 3) == 0) {
                atomicAdd(ssm + warpM * 64 + m * 16 + qr, p0);
                atomicAdd(ssm + warpM * 64 + m * 16 + qr + 8, p1);
            }
        }
        __syncthreads();
        __half* Q = (__half*)C0;
        #pragma unroll
        for (int m = 0; m < 4; m++) {
            const int lr0 = warpM * 64 + m * 16 + qr, lr1 = lr0 + 8;
            const float i0 = rsqrtf(ssm[lr0] + EPSN);
            const float i1 = rsqrtf(ssm[lr1] + EPSN);
            const int r0 = bm + lr0, r1 = bm + lr1;
            #pragma unroll
            for (int n = 0; n < 4; n++) {
                const int c = bn + warpN * 32 + n * 8 + qc;
                *reinterpret_cast<uint32_t*>(Q + (long long)r0 * ldc + c) =
                    packh2(acc[m][n][0] * i0, acc[m][n][1] * i0);
                *reinterpret_cast<uint32_t*>(Q + (long long)r1 * ldc + c) =
                    packh2(acc[m][n][2] * i1, acc[m][n][3] * i1);
            }
        }
    }
}

// ---------------- fused attention (fp16): S=Q*K^T 1-pass, y=P*V 1-pass --------
// CTA: 128 q-rows x 1 head, 16 KV tiles of 128 slots. Q,K,V single fp16.
// P stays in registers. exp + rowsum folded into the PV loop so MUFU overlaps
// with HMMA instead of forming a serial phase.
#define PITCH 272
#define MATB  (128 * PITCH)        // 34816 B
#define FA_Q  0
#define FA_K  MATB
#define FA_V  (2 * MATB)
#define FA_TOT (3 * MATB)          // 104448 B

__global__ void __launch_bounds__(256, 1)
fused_attn(const __half* __restrict__ qn, const __half* __restrict__ kh,
           const __half* __restrict__ vh,
           __nv_bfloat16* __restrict__ yh, __nv_bfloat16* __restrict__ yl)
{
    extern __shared__ char smch[];
    const uint32_t smb = s2u(smch);
    const int tid = threadIdx.x, lane = tid & 31, wid = tid >> 5;
    const int bm = blockIdx.x * 128, h = blockIdx.y;
    const int row16 = tid >> 4, c16 = tid & 15;

    // Q tile (fp16 single): 128 rows x 256 B
    #pragma unroll
    for (int i = 0; i < 8; i++) {
        const int r = row16 + i * 16;
        cpasync16(smb + FA_Q + r * PITCH + c16 * 16,
                  qn + (size_t)(bm + r) * DM + h * HD + c16 * 8);
    }
    asm volatile("cp.async.commit_group;" ::: "memory");

    auto load_k = [&](int j) {
        const __half* s = kh + ((size_t)h * NK + j * 128) * HD;
        #pragma unroll
        for (int i = 0; i < 8; i++) {
            const int r = row16 + i * 16;
            cpasync16(smb + FA_K + r * PITCH + c16 * 16, s + (size_t)r * HD + c16 * 8);
        }
        asm volatile("cp.async.commit_group;" ::: "memory");
    };
    auto load_v = [&](int j) {
        const __half* s = vh + (size_t)h * HD * NK + j * 128;
        #pragma unroll
        for (int i = 0; i < 8; i++) {
            const int r = row16 + i * 16;           // d index
            cpasync16(smb + FA_V + r * PITCH + c16 * 16, s + (size_t)r * NK + c16 * 8);
        }
        asm volatile("cp.async.commit_group;" ::: "memory");
    };

    load_k(0);
    load_v(0);

    const int aLR = (lane & 7) + ((lane >> 3) & 1) * 8;
    const int aLK = (lane >> 4) * 8;
    const int bLR = (lane & 7) + (lane >> 4) * 8;
    const int bLK = ((lane >> 3) & 1) * 8;
    const uint32_t aBase = (uint32_t)(wid * 16 + aLR) * PITCH + aLK * 2;
    const uint32_t bBase = (uint32_t)bLR * PITCH + bLK * 2;

    float accy[16][4] = {};
    float s0 = 0.0f, s1 = 0.0f;

    for (int j = 0; j < 16; j++) {
        float accs[16][4] = {};

        asm volatile("cp.async.wait_group 1;" ::: "memory");   // K_j ready
        __syncthreads();

        // ---- S = Q * K^T (fp16, single pass) ----
        #pragma unroll
        for (int t = 0; t < 8; t++) {
            uint32_t a[4];
            ldsm4(a, smb + FA_Q + aBase + t * 32);
            #pragma unroll
            for (int p = 0; p < 8; p++) {
                uint32_t b[4];
                ldsm4(b, smb + FA_K + (uint32_t)p * 16 * PITCH + bBase + t * 32);
                mma_h(accs[2 * p],     a, b);
                mma_h(accs[2 * p + 1], a, b + 2);
            }
        }
        __syncthreads();
        if (j + 1 < 16) load_k(j + 1);

        asm volatile("cp.async.wait_group 1;" ::: "memory");   // V_j ready
        __syncthreads();

        // ---- y += P * V; exp + rowsum folded per t so MUFU overlaps HMMA ----
        #pragma unroll
        for (int t = 0; t < 8; t++) {
            uint32_t pf[4];
            {
                float* e0 = accs[2 * t];
                float* e1 = accs[2 * t + 1];
                e0[0] = __expf(e0[0]); e0[1] = __expf(e0[1]);
                e0[2] = __expf(e0[2]); e0[3] = __expf(e0[3]);
                e1[0] = __expf(e1[0]); e1[1] = __expf(e1[1]);
                e1[2] = __expf(e1[2]); e1[3] = __expf(e1[3]);
                s0 += e0[0] + e0[1] + e1[0] + e1[1];
                s1 += e0[2] + e0[3] + e1[2] + e1[3];
                pf[0] = packh2(e0[0], e0[1]);
                pf[1] = packh2(e0[2], e0[3]);
                pf[2] = packh2(e1[0], e1[1]);
                pf[3] = packh2(e1[2], e1[3]);
            }
            #pragma unroll
            for (int p = 0; p < 8; p++) {
                uint32_t b[4];
                ldsm4(b, smb + FA_V + (uint32_t)p * 16 * PITCH + bBase + t * 32);
                mma_h(accy[2 * p],     pf, b);
                mma_h(accy[2 * p + 1], pf, b + 2);
            }
        }
        __syncthreads();
        if (j + 1 < 16) load_v(j + 1);
    }

    // ---- epilogue: /rowsum, bf16 hi/lo split, store ----
    s0 += __shfl_xor_sync(0xffffffffu, s0, 1);
    s0 += __shfl_xor_sync(0xffffffffu, s0, 2);
    s1 += __shfl_xor_sync(0xffffffffu, s1, 1);
    s1 += __shfl_xor_sync(0xffffffffu, s1, 2);
    const float inv0 = 1.0f / s0, inv1 = 1.0f / s1;

    const int qr = lane >> 2, qc = (lane & 3) * 2;
    const int r0 = bm + wid * 16 + qr, r1 = r0 + 8;
    #pragma unroll
    for (int n = 0; n < 16; n++) {
        const int c = h * HD + n * 8 + qc;
        float e0 = accy[n][0] * inv0, e1 = accy[n][1] * inv0;
        float e2 = accy[n][2] * inv1, e3 = accy[n][3] * inv1;
        float h0 = bfhi(e0), h1 = bfhi(e1), h2 = bfhi(e2), h3 = bfhi(e3);
        *reinterpret_cast<uint32_t*>(yh + (size_t)r0 * DM + c) = packbf2(h0, h1);
        *reinterpret_cast<uint32_t*>(yl + (size_t)r0 * DM + c) = packbf2(e0 - h0, e1 - h1);
        *reinterpret_cast<uint32_t*>(yh + (size_t)r1 * DM + c) = packbf2(h2, h3);
        *reinterpret_cast<uint32_t*>(yl + (size_t)r1 * DM + c) = packbf2(e2 - h2, e3 - h3);
    }
}

// ---------------- prep kernels ------------------------------------------------
__global__ void split4_kernel(const float* __restrict__ s, __nv_bfloat16* __restrict__ h,
                              __nv_bfloat16* __restrict__ l, int n4)
{
    const int i = blockIdx.x * 256 + threadIdx.x;
    if (i >= n4) return;
    float4 x = reinterpret_cast<const float4*>(s)[i];
    float ha = bfhi(x.x), hb = bfhi(x.y), hc = bfhi(x.z), hd = bfhi(x.w);
    reinterpret_cast<uint2*>(h)[i] = make_uint2(packbf2(ha, hb), packbf2(hc, hd));
    reinterpret_cast<uint2*>(l)[i] = make_uint2(packbf2(x.x - ha, x.y - hb), packbf2(x.z - hc, x.w - hd));
}

__global__ void transpose_split_kernel(const float* __restrict__ W, __nv_bfloat16* __restrict__ Th,
                                       __nv_bfloat16* __restrict__ Tl, int R, int C)
{
    __shared__ float tile[32][33];
    const int r0 = blockIdx.y * 32, c0 = blockIdx.x * 32;
    for (int i = threadIdx.y; i < 32; i += 8)
        tile[i][threadIdx.x] = W[(long long)(r0 + i) * C + c0 + threadIdx.x];
    __syncthreads();
    for (int i = threadIdx.y; i < 32; i += 8) {
        float x = tile[threadIdx.x][i];
        float hh = bfhi(x);
        long long o = (long long)(c0 + i) * R + r0 + threadIdx.x;
        Th[o] = __float2bfloat16_rn(x);
        Tl[o] = __float2bfloat16_rn(x - hh);
    }
}

// keys: row n = k*NH+h -> normalized*scale, fp16 single, layout [h][k][d]
__global__ void prep_k_kernel(const float* __restrict__ keys, const float* __restrict__ scale,
                              __half* __restrict__ kout)
{
    const int seg = blockIdx.x * 8 + (threadIdx.x >> 5);
    const int lane = threadIdx.x & 31;
    const int k = seg / NH, h = seg % NH;
    float4 x = reinterpret_cast<const float4*>(keys + (size_t)seg * HD)[lane];
    float ss = x.x * x.x + x.y * x.y + x.z * x.z + x.w * x.w;
    #pragma unroll
    for (int o = 16; o > 0; o >>= 1) ss += __shfl_xor_sync(0xffffffffu, ss, o);
    const float rr = rsqrtf(ss + EPSN) * scale[h];
    const size_t base = ((size_t)h * NK + k) * HD;
    reinterpret_cast<uint2*>(kout + base)[lane] =
        make_uint2(packh2(x.x * rr, x.y * rr), packh2(x.z * rr, x.w * rr));
}

// values: [k][h][d] -> vT[h][d][k], fp16 single
__global__ void prep_v_kernel(const float* __restrict__ values, __half* __restrict__ vout)
{
    __shared__ float tile[32][33];
    const int h = blockIdx.z, k0 = blockIdx.x * 32, d0 = blockIdx.y * 32;
    for (int i = threadIdx.y; i < 32; i += 8)
        tile[i][threadIdx.x] = values[((size_t)(k0 + i) * NH + h) * HD + d0 + threadIdx.x];
    __syncthreads();
    for (int i = threadIdx.y; i < 32; i += 8) {
        size_t o = ((size_t)h * HD + d0 + i) * NK + k0 + threadIdx.x;
        vout[o] = __float2half_rn(tile[threadIdx.x][i]);
    }
}

// ---------------- launch ------------------------------------------------------
extern "C" void kernel_launch(void* const* d_in, const int* in_sizes, int n_in,
                              void* d_out, int out_size)
{
    const float* x      = (const float*)d_in[0];
    const float* Wq     = (const float*)d_in[1];
    const float* keys   = (const float*)d_in[2];
    const float* values = (const float*)d_in[3];
    const float* scale  = (const float*)d_in[4];
    const float* Wo     = (const float*)d_in[5];
    float* out = (float*)d_out;

    __nv_bfloat16 *pxh, *pxl, *pwqh, *pwql, *pwoh, *pwol, *pyh, *pyl;
    __half *pqn, *pkh, *pvh;
    cudaGetSymbolAddress((void**)&pxh, g_xh);   cudaGetSymbolAddress((void**)&pxl, g_xl);
    cudaGetSymbolAddress((void**)&pwqh, g_wqh); cudaGetSymbolAddress((void**)&pwql, g_wql);
    cudaGetSymbolAddress((void**)&pwoh, g_woh); cudaGetSymbolAddress((void**)&pwol, g_wol);
    cudaGetSymbolAddress((void**)&pqn, g_qn);
    cudaGetSymbolAddress((void**)&pkh, g_kh);
    cudaGetSymbolAddress((void**)&pvh, g_vh);
    cudaGetSymbolAddress((void**)&pyh, g_yh);   cudaGetSymbolAddress((void**)&pyl, g_yl);

    cudaFuncSetAttribute(mma_gemm<0>, cudaFuncAttributeMaxDynamicSharedMemorySize, SMEM_TOT);
    cudaFuncSetAttribute(mma_gemm<3>, cudaFuncAttributeMaxDynamicSharedMemorySize, SMEM_TOT);
    cudaFuncSetAttribute(fused_attn, cudaFuncAttributeMaxDynamicSharedMemorySize, FA_TOT);

    // prep
    split4_kernel<<<(S_LEN * DM / 4 + 255) / 256, 256>>>(x, pxh, pxl, S_LEN * DM / 4);
    transpose_split_kernel<<<dim3(DM / 32, DM / 32), dim3(32, 8)>>>(Wq, pwqh, pwql, DM, DM);
    transpose_split_kernel<<<dim3(DM / 32, DM / 32), dim3(32, 8)>>>(Wo, pwoh, pwol, DM, DM);
    prep_k_kernel<<<(NK * NH) / 8, 256>>>(keys, scale, pkh);
    prep_v_kernel<<<dim3(NK / 32, HD / 32, NH), dim3(32, 8)>>>(values, pvh);

    // 1) q = normalize(x @ Wq) -> fp16 (normalization fused into epilogue)
    mma_gemm<3><<<dim3(DM / 128, S_LEN / 128, 1), 256, SMEM_TOT>>>(
        pxh, pxl, pwqh, pwql, pqn, DM, DM, DM, DM);

    // 2) fused attention (fp16): scores + softmax + P@V -> y bf16 hi/lo
    fused_attn<<<dim3(S_LEN / 128, NH), 256, FA_TOT>>>(
        pqn, pkh, pvh, pyh, pyl);

    // 3) out = y @ Wo (bf16 3-pass, fp32 out)
    mma_gemm<0><<<dim3(DM / 128, S_LEN / 128, 1), 256, SMEM_TOT>>>(
        pyh, pyl, pwoh, pwol, out, DM, DM, DM, DM);
}

// round 13
// speedup vs baseline: 5.3568x; 1.0659x over previous
#include <cuda_runtime.h>
#include <cuda_bf16.h>
#include <cuda_fp16.h>
#include <cstdint>
#include <math.h>

#define S_LEN 4096
#define DM    1024
#define NH    8
#define HD    128
#define NK    2048
#define EPSN  1e-6f

// ---------------- scratch (device globals; no allocation allowed) -------------
__device__ __nv_bfloat16 g_xh[(size_t)S_LEN * DM], g_xl[(size_t)S_LEN * DM];
__device__ __nv_bfloat16 g_wqh[(size_t)DM * DM],   g_wql[(size_t)DM * DM];
__device__ __half        g_woh[(size_t)DM * DM],   g_wol[(size_t)DM * DM];   // Wo^T fp16 hi/lo
__device__ __half        g_qn[(size_t)S_LEN * DM];          // normalized q, fp16
__device__ __half        g_kh[(size_t)NH * NK * HD];        // normalized*scaled K, fp16
__device__ __half        g_vh[(size_t)NH * HD * NK];        // V^T, fp16 single
__device__ __half        g_y[(size_t)S_LEN * DM];           // attention out, fp16 single

// ---------------- helpers -----------------------------------------------------
__device__ __forceinline__ uint32_t s2u(const void* p) {
    uint32_t a;
    asm("{ .reg .u64 t; cvta.to.shared.u64 t, %1; cvt.u32.u64 %0, t; }" : "=r"(a) : "l"(p));
    return a;
}
__device__ __forceinline__ float bfhi(float x) { return __bfloat162float(__float2bfloat16_rn(x)); }
__device__ __forceinline__ uint32_t packbf2(float a, float b) {
    __nv_bfloat162 t = __floats2bfloat162_rn(a, b);
    return reinterpret_cast<uint32_t&>(t);
}
__device__ __forceinline__ uint32_t packh2(float a, float b) {
    __half2 t = __floats2half2_rn(a, b);
    return reinterpret_cast<uint32_t&>(t);
}
__device__ __forceinline__ void cpasync16(uint32_t dst, const void* src) {
    asm volatile("cp.async.cg.shared.global [%0], [%1], 16;" :: "r"(dst), "l"(src));
}
__device__ __forceinline__ void ldsm4(uint32_t* r, uint32_t addr) {
    asm volatile("ldmatrix.sync.aligned.m8n8.x4.shared.b16 {%0,%1,%2,%3}, [%4];"
        : "=r"(r[0]), "=r"(r[1]), "=r"(r[2]), "=r"(r[3]) : "r"(addr));
}
__device__ __forceinline__ void mma16816(float* c, const uint32_t* a, const uint32_t* b) {
    asm volatile("mma.sync.aligned.m16n8k16.row.col.f32.bf16.bf16.f32 "
        "{%0,%1,%2,%3}, {%4,%5,%6,%7}, {%8,%9}, {%0,%1,%2,%3};"
        : "+f"(c[0]), "+f"(c[1]), "+f"(c[2]), "+f"(c[3])
        : "r"(a[0]), "r"(a[1]), "r"(a[2]), "r"(a[3]), "r"(b[0]), "r"(b[1]));
}
__device__ __forceinline__ void mma_h(float* c, const uint32_t* a, const uint32_t* b) {
    asm volatile("mma.sync.aligned.m16n8k16.row.col.f32.f16.f16.f32 "
        "{%0,%1,%2,%3}, {%4,%5,%6,%7}, {%8,%9}, {%0,%1,%2,%3};"
        : "+f"(c[0]), "+f"(c[1]), "+f"(c[2]), "+f"(c[3])
        : "r"(a[0]), "r"(a[1]), "r"(a[2]), "r"(a[3]), "r"(b[0]), "r"(b[1]));
}

#define ROWB  80
#define TILEB (128 * ROWB)

// ---------------- bf16-split GEMM (3 passes), q-projection -------------------
// EPI 3: per-row L2-normalize over the 128-col tile (= one head) -> fp16.
#define SMEM_TOT (8 * TILEB)

__global__ void __launch_bounds__(256, 2)
mma_gemm_q(const __nv_bfloat16* __restrict__ Ah, const __nv_bfloat16* __restrict__ Al,
           const __nv_bfloat16* __restrict__ Bh, const __nv_bfloat16* __restrict__ Bl,
           __half* __restrict__ C0, int K, int lda, int ldb, int ldc)
{
    extern __shared__ char smch[];
    const uint32_t smb = s2u(smch);
    const int tid = threadIdx.x, lane = tid & 31, wid = tid >> 5;
    const int warpM = wid & 1, warpN = wid >> 1;
    const int bm = blockIdx.y * 128, bn = blockIdx.x * 128;

    const __nv_bfloat16* src[4];
    src[0] = Ah + (long long)bm * lda;
    src[1] = Al + (long long)bm * lda;
    src[2] = Bh + (long long)bn * ldb;
    src[3] = Bl + (long long)bn * ldb;

    const int aLR = (lane & 7) + ((lane >> 3) & 1) * 8;
    const int aLK = (lane >> 4) * 8;
    const int bLR = (lane & 7) + (lane >> 4) * 8;
    const int bLK = ((lane >> 3) & 1) * 8;
    int aOff[4], bOff[2];
    #pragma unroll
    for (int m = 0; m < 4; m++) aOff[m] = (warpM * 64 + m * 16 + aLR) * ROWB + aLK * 2;
    #pragma unroll
    for (int p = 0; p < 2; p++) bOff[p] = (warpN * 32 + p * 16 + bLR) * ROWB + bLK * 2;

    float acc[4][4][4] = {};
    const int nCh = K >> 5;

    auto load_stage = [&](int st, int k0) {
        #pragma unroll
        for (int w = 0; w < 4; w++) {
            const __nv_bfloat16* s = src[w] + k0;
            const int ld = (w < 2) ? lda : ldb;
            const uint32_t dst = smb + (uint32_t)(st * 4 + w) * TILEB;
            #pragma unroll
            for (int i = 0; i < 2; i++) {
                const int u = tid + i * 256;
                const int row = u >> 2, c = u & 3;
                cpasync16(dst + row * ROWB + c * 16, s + (long long)row * ld + c * 8);
            }
        }
    };

    load_stage(0, 0);
    asm volatile("cp.async.commit_group;" ::: "memory");

    for (int t = 0; t < nCh; t++) {
        if (t + 1 < nCh) {
            load_stage((t + 1) & 1, (t + 1) * 32);
            asm volatile("cp.async.commit_group;" ::: "memory");
            asm volatile("cp.async.wait_group 1;" ::: "memory");
        } else {
            asm volatile("cp.async.wait_group 0;" ::: "memory");
        }
        __syncthreads();

        const uint32_t base = smb + (uint32_t)((t & 1) * 4) * TILEB;
        #pragma unroll
        for (int kk = 0; kk < 2; kk++) {
            uint32_t bh[8], bl[8];
            #pragma unroll
            for (int p = 0; p < 2; p++) {
                ldsm4(bh + 4 * p, base + 2 * TILEB + bOff[p] + kk * 32);
                ldsm4(bl + 4 * p, base + 3 * TILEB + bOff[p] + kk * 32);
            }
            #pragma unroll
            for (int m = 0; m < 4; m++) {
                uint32_t ah[4], al[4];
                ldsm4(ah, base + 0 * TILEB + aOff[m] + kk * 32);
                ldsm4(al, base + 1 * TILEB + aOff[m] + kk * 32);
                #pragma unroll
                for (int n = 0; n < 4; n++) {
                    mma16816(acc[m][n], ah, bh + 2 * n);
                    mma16816(acc[m][n], ah, bl + 2 * n);
                    mma16816(acc[m][n], al, bh + 2 * n);
                }
            }
        }
        __syncthreads();
    }

    const int qr = lane >> 2, qc = (lane & 3) * 2;

    // per-row L2 normalize across this 128-col tile (one head), write fp16
    float* ssm = (float*)smch;
    if (tid < 128) ssm[tid] = 0.0f;
    __syncthreads();
    #pragma unroll
    for (int m = 0; m < 4; m++) {
        float p0 = 0.0f, p1 = 0.0f;
        #pragma unroll
        for (int n = 0; n < 4; n++) {
            p0 += acc[m][n][0] * acc[m][n][0] + acc[m][n][1] * acc[m][n][1];
            p1 += acc[m][n][2] * acc[m][n][2] + acc[m][n][3] * acc[m][n][3];
        }
        p0 += __shfl_xor_sync(0xffffffffu, p0, 1);
        p0 += __shfl_xor_sync(0xffffffffu, p0, 2);
        p1 += __shfl_xor_sync(0xffffffffu, p1, 1);
        p1 += __shfl_xor_sync(0xffffffffu, p1, 2);
        if ((lane & 3) == 0) {
            atomicAdd(ssm + warpM * 64 + m * 16 + qr, p0);
            atomicAdd(ssm + warpM * 64 + m * 16 + qr + 8, p1);
        }
    }
    __syncthreads();
    #pragma unroll
    for (int m = 0; m < 4; m++) {
        const int lr0 = warpM * 64 + m * 16 + qr, lr1 = lr0 + 8;
        const float i0 = rsqrtf(ssm[lr0] + EPSN);
        const float i1 = rsqrtf(ssm[lr1] + EPSN);
        const int r0 = bm + lr0, r1 = bm + lr1;
        #pragma unroll
        for (int n = 0; n < 4; n++) {
            const int c = bn + warpN * 32 + n * 8 + qc;
            *reinterpret_cast<uint32_t*>(C0 + (long long)r0 * ldc + c) =
                packh2(acc[m][n][0] * i0, acc[m][n][1] * i0);
            *reinterpret_cast<uint32_t*>(C0 + (long long)r1 * ldc + c) =
                packh2(acc[m][n][2] * i1, acc[m][n][3] * i1);
        }
    }
}

// ---------------- fp16 2-pass GEMM, out-projection ----------------------------
// C = A * (Bh + Bl)^T, A fp16 single [M][K], B fp16 hi/lo [N][K], fp32 out.
#define SMEMH_TOT (6 * TILEB)

__global__ void __launch_bounds__(256, 2)
mma_gemm_o(const __half* __restrict__ A,
           const __half* __restrict__ Bh, const __half* __restrict__ Bl,
           float* __restrict__ C0, int K, int lda, int ldb, int ldc)
{
    extern __shared__ char smch[];
    const uint32_t smb = s2u(smch);
    const int tid = threadIdx.x, lane = tid & 31, wid = tid >> 5;
    const int warpM = wid & 1, warpN = wid >> 1;
    const int bm = blockIdx.y * 128, bn = blockIdx.x * 128;

    const __half* src[3];
    src[0] = A + (long long)bm * lda;
    src[1] = Bh + (long long)bn * ldb;
    src[2] = Bl + (long long)bn * ldb;

    const int aLR = (lane & 7) + ((lane >> 3) & 1) * 8;
    const int aLK = (lane >> 4) * 8;
    const int bLR = (lane & 7) + (lane >> 4) * 8;
    const int bLK = ((lane >> 3) & 1) * 8;
    int aOff[4], bOff[2];
    #pragma unroll
    for (int m = 0; m < 4; m++) aOff[m] = (warpM * 64 + m * 16 + aLR) * ROWB + aLK * 2;
    #pragma unroll
    for (int p = 0; p < 2; p++) bOff[p] = (warpN * 32 + p * 16 + bLR) * ROWB + bLK * 2;

    float acc[4][4][4] = {};
    const int nCh = K >> 5;

    auto load_stage = [&](int st, int k0) {
        #pragma unroll
        for (int w = 0; w < 3; w++) {
            const __half* s = src[w] + k0;
            const int ld = (w < 1) ? lda : ldb;
            const uint32_t dst = smb + (uint32_t)(st * 3 + w) * TILEB;
            #pragma unroll
            for (int i = 0; i < 2; i++) {
                const int u = tid + i * 256;
                const int row = u >> 2, c = u & 3;
                cpasync16(dst + row * ROWB + c * 16, s + (long long)row * ld + c * 8);
            }
        }
    };

    load_stage(0, 0);
    asm volatile("cp.async.commit_group;" ::: "memory");

    for (int t = 0; t < nCh; t++) {
        if (t + 1 < nCh) {
            load_stage((t + 1) & 1, (t + 1) * 32);
            asm volatile("cp.async.commit_group;" ::: "memory");
            asm volatile("cp.async.wait_group 1;" ::: "memory");
        } else {
            asm volatile("cp.async.wait_group 0;" ::: "memory");
        }
        __syncthreads();

        const uint32_t base = smb + (uint32_t)((t & 1) * 3) * TILEB;
        #pragma unroll
        for (int kk = 0; kk < 2; kk++) {
            uint32_t bh[8], bl[8];
            #pragma unroll
            for (int p = 0; p < 2; p++) {
                ldsm4(bh + 4 * p, base + 1 * TILEB + bOff[p] + kk * 32);
                ldsm4(bl + 4 * p, base + 2 * TILEB + bOff[p] + kk * 32);
            }
            #pragma unroll
            for (int m = 0; m < 4; m++) {
                uint32_t a[4];
                ldsm4(a, base + aOff[m] + kk * 32);
                #pragma unroll
                for (int n = 0; n < 4; n++) {
                    mma_h(acc[m][n], a, bh + 2 * n);
                    mma_h(acc[m][n], a, bl + 2 * n);
                }
            }
        }
        __syncthreads();
    }

    const int qr = lane >> 2, qc = (lane & 3) * 2;
    #pragma unroll
    for (int m = 0; m < 4; m++) {
        const int r0 = bm + warpM * 64 + m * 16 + qr;
        const int r1 = r0 + 8;
        #pragma unroll
        for (int n = 0; n < 4; n++) {
            const int c = bn + warpN * 32 + n * 8 + qc;
            *reinterpret_cast<float2*>(C0 + (long long)r0 * ldc + c) =
                make_float2(acc[m][n][0], acc[m][n][1]);
            *reinterpret_cast<float2*>(C0 + (long long)r1 * ldc + c) =
                make_float2(acc[m][n][2], acc[m][n][3]);
        }
    }
}

// ---------------- fused attention: 64 q-rows, 128 threads, occupancy 2 --------
// Q,K,V single fp16. Each of 4 warps: 16 rows x all 128 slots / 128 d.
// P stays in registers; exp+rowsum folded into PV loop. y out fp16 single.
#define PITCH 272
#define QMATB (64 * PITCH)         // 17408
#define KVMATB (128 * PITCH)       // 34816
#define FA_Q  0
#define FA_K  QMATB
#define FA_V  (QMATB + KVMATB)
#define FA_TOT (QMATB + 2 * KVMATB)   // 87040

__global__ void __launch_bounds__(128, 2)
fused_attn(const __half* __restrict__ qn, const __half* __restrict__ kh,
           const __half* __restrict__ vh, __half* __restrict__ y)
{
    extern __shared__ char smch[];
    const uint32_t smb = s2u(smch);
    const int tid = threadIdx.x, lane = tid & 31, wid = tid >> 5;
    const int bm = blockIdx.x * 64, h = blockIdx.y;
    const int row8 = tid >> 4, c16 = tid & 15;   // 128 threads: 8 rows x 16 chunks

    // Q tile: 64 rows x 256 B
    #pragma unroll
    for (int i = 0; i < 8; i++) {
        const int r = row8 + i * 8;
        cpasync16(smb + FA_Q + r * PITCH + c16 * 16,
                  qn + (size_t)(bm + r) * DM + h * HD + c16 * 8);
    }
    asm volatile("cp.async.commit_group;" ::: "memory");

    auto load_k = [&](int j) {
        const __half* s = kh + ((size_t)h * NK + j * 128) * HD;
        #pragma unroll
        for (int i = 0; i < 16; i++) {
            const int r = row8 + i * 8;
            cpasync16(smb + FA_K + r * PITCH + c16 * 16, s + (size_t)r * HD + c16 * 8);
        }
        asm volatile("cp.async.commit_group;" ::: "memory");
    };
    auto load_v = [&](int j) {
        const __half* s = vh + (size_t)h * HD * NK + j * 128;
        #pragma unroll
        for (int i = 0; i < 16; i++) {
            const int r = row8 + i * 8;             // d index
            cpasync16(smb + FA_V + r * PITCH + c16 * 16, s + (size_t)r * NK + c16 * 8);
        }
        asm volatile("cp.async.commit_group;" ::: "memory");
    };

    load_k(0);
    load_v(0);

    const int aLR = (lane & 7) + ((lane >> 3) & 1) * 8;
    const int aLK = (lane >> 4) * 8;
    const int bLR = (lane & 7) + (lane >> 4) * 8;
    const int bLK = ((lane >> 3) & 1) * 8;
    const uint32_t aBase = (uint32_t)(wid * 16 + aLR) * PITCH + aLK * 2;
    const uint32_t bBase = (uint32_t)bLR * PITCH + bLK * 2;

    float accy[16][4] = {};
    float s0 = 0.0f, s1 = 0.0f;

    for (int j = 0; j < 16; j++) {
        float accs[16][4] = {};

        asm volatile("cp.async.wait_group 1;" ::: "memory");   // K_j ready
        __syncthreads();

        // ---- S = Q * K^T ----
        #pragma unroll
        for (int t = 0; t < 8; t++) {
            uint32_t a[4];
            ldsm4(a, smb + FA_Q + aBase + t * 32);
            #pragma unroll
            for (int p = 0; p < 8; p++) {
                uint32_t b[4];
                ldsm4(b, smb + FA_K + (uint32_t)p * 16 * PITCH + bBase + t * 32);
                mma_h(accs[2 * p],     a, b);
                mma_h(accs[2 * p + 1], a, b + 2);
            }
        }
        __syncthreads();
        if (j + 1 < 16) load_k(j + 1);

        asm volatile("cp.async.wait_group 1;" ::: "memory");   // V_j ready
        __syncthreads();

        // ---- y += P * V; exp + rowsum folded per t ----
        #pragma unroll
        for (int t = 0; t < 8; t++) {
            uint32_t pf[4];
            {
                float* e0 = accs[2 * t];
                float* e1 = accs[2 * t + 1];
                e0[0] = __expf(e0[0]); e0[1] = __expf(e0[1]);
                e0[2] = __expf(e0[2]); e0[3] = __expf(e0[3]);
                e1[0] = __expf(e1[0]); e1[1] = __expf(e1[1]);
                e1[2] = __expf(e1[2]); e1[3] = __expf(e1[3]);
                s0 += e0[0] + e0[1] + e1[0] + e1[1];
                s1 += e0[2] + e0[3] + e1[2] + e1[3];
                pf[0] = packh2(e0[0], e0[1]);
                pf[1] = packh2(e0[2], e0[3]);
                pf[2] = packh2(e1[0], e1[1]);
                pf[3] = packh2(e1[2], e1[3]);
            }
            #pragma unroll
            for (int p = 0; p < 8; p++) {
                uint32_t b[4];
                ldsm4(b, smb + FA_V + (uint32_t)p * 16 * PITCH + bBase + t * 32);
                mma_h(accy[2 * p],     pf, b);
                mma_h(accy[2 * p + 1], pf, b + 2);
            }
        }
        __syncthreads();
        if (j + 1 < 16) load_v(j + 1);
    }

    // ---- epilogue: /rowsum, write fp16 ----
    s0 += __shfl_xor_sync(0xffffffffu, s0, 1);
    s0 += __shfl_xor_sync(0xffffffffu, s0, 2);
    s1 += __shfl_xor_sync(0xffffffffu, s1, 1);
    s1 += __shfl_xor_sync(0xffffffffu, s1, 2);
    const float inv0 = 1.0f / s0, inv1 = 1.0f / s1;

    const int qr = lane >> 2, qc = (lane & 3) * 2;
    const int r0 = bm + wid * 16 + qr, r1 = r0 + 8;
    #pragma unroll
    for (int n = 0; n < 16; n++) {
        const int c = h * HD + n * 8 + qc;
        *reinterpret_cast<uint32_t*>(y + (size_t)r0 * DM + c) =
            packh2(accy[n][0] * inv0, accy[n][1] * inv0);
        *reinterpret_cast<uint32_t*>(y + (size_t)r1 * DM + c) =
            packh2(accy[n][2] * inv1, accy[n][3] * inv1);
    }
}

// ---------------- prep kernels ------------------------------------------------
__global__ void split4_kernel(const float* __restrict__ s, __nv_bfloat16* __restrict__ h,
                              __nv_bfloat16* __restrict__ l, int n4)
{
    const int i = blockIdx.x * 256 + threadIdx.x;
    if (i >= n4) return;
    float4 x = reinterpret_cast<const float4*>(s)[i];
    float ha = bfhi(x.x), hb = bfhi(x.y), hc = bfhi(x.z), hd = bfhi(x.w);
    reinterpret_cast<uint2*>(h)[i] = make_uint2(packbf2(ha, hb), packbf2(hc, hd));
    reinterpret_cast<uint2*>(l)[i] = make_uint2(packbf2(x.x - ha, x.y - hb), packbf2(x.z - hc, x.w - hd));
}

__global__ void transpose_split_kernel(const float* __restrict__ W, __nv_bfloat16* __restrict__ Th,
                                       __nv_bfloat16* __restrict__ Tl, int R, int C)
{
    __shared__ float tile[32][33];
    const int r0 = blockIdx.y * 32, c0 = blockIdx.x * 32;
    for (int i = threadIdx.y; i < 32; i += 8)
        tile[i][threadIdx.x] = W[(long long)(r0 + i) * C + c0 + threadIdx.x];
    __syncthreads();
    for (int i = threadIdx.y; i < 32; i += 8) {
        float x = tile[threadIdx.x][i];
        float hh = bfhi(x);
        long long o = (long long)(c0 + i) * R + r0 + threadIdx.x;
        Th[o] = __float2bfloat16_rn(x);
        Tl[o] = __float2bfloat16_rn(x - hh);
    }
}

// transpose + fp16 hi/lo split (for Wo)
__global__ void transpose_split_h_kernel(const float* __restrict__ W, __half* __restrict__ Th,
                                         __half* __restrict__ Tl, int R, int C)
{
    __shared__ float tile[32][33];
    const int r0 = blockIdx.y * 32, c0 = blockIdx.x * 32;
    for (int i = threadIdx.y; i < 32; i += 8)
        tile[i][threadIdx.x] = W[(long long)(r0 + i) * C + c0 + threadIdx.x];
    __syncthreads();
    for (int i = threadIdx.y; i < 32; i += 8) {
        float x = tile[threadIdx.x][i];
        __half hx = __float2half_rn(x);
        long long o = (long long)(c0 + i) * R + r0 + threadIdx.x;
        Th[o] = hx;
        Tl[o] = __float2half_rn(x - __half2float(hx));
    }
}

// keys: row n = k*NH+h -> normalized*scale, fp16, layout [h][k][d]
__global__ void prep_k_kernel(const float* __restrict__ keys, const float* __restrict__ scale,
                              __half* __restrict__ kout)
{
    const int seg = blockIdx.x * 8 + (threadIdx.x >> 5);
    const int lane = threadIdx.x & 31;
    const int k = seg / NH, h = seg % NH;
    float4 x = reinterpret_cast<const float4*>(keys + (size_t)seg * HD)[lane];
    float ss = x.x * x.x + x.y * x.y + x.z * x.z + x.w * x.w;
    #pragma unroll
    for (int o = 16; o > 0; o >>= 1) ss += __shfl_xor_sync(0xffffffffu, ss, o);
    const float rr = rsqrtf(ss + EPSN) * scale[h];
    const size_t base = ((size_t)h * NK + k) * HD;
    reinterpret_cast<uint2*>(kout + base)[lane] =
        make_uint2(packh2(x.x * rr, x.y * rr), packh2(x.z * rr, x.w * rr));
}

// values: [k][h][d] -> vT[h][d][k], fp16
__global__ void prep_v_kernel(const float* __restrict__ values, __half* __restrict__ vout)
{
    __shared__ float tile[32][33];
    const int h = blockIdx.z, k0 = blockIdx.x * 32, d0 = blockIdx.y * 32;
    for (int i = threadIdx.y; i < 32; i += 8)
        tile[i][threadIdx.x] = values[((size_t)(k0 + i) * NH + h) * HD + d0 + threadIdx.x];
    __syncthreads();
    for (int i = threadIdx.y; i < 32; i += 8) {
        size_t o = ((size_t)h * HD + d0 + i) * NK + k0 + threadIdx.x;
        vout[o] = __float2half_rn(tile[threadIdx.x][i]);
    }
}

// ---------------- launch ------------------------------------------------------
extern "C" void kernel_launch(void* const* d_in, const int* in_sizes, int n_in,
                              void* d_out, int out_size)
{
    const float* x      = (const float*)d_in[0];
    const float* Wq     = (const float*)d_in[1];
    const float* keys   = (const float*)d_in[2];
    const float* values = (const float*)d_in[3];
    const float* scale  = (const float*)d_in[4];
    const float* Wo     = (const float*)d_in[5];
    float* out = (float*)d_out;

    __nv_bfloat16 *pxh, *pxl, *pwqh, *pwql;
    __half *pwoh, *pwol, *pqn, *pkh, *pvh, *py;
    cudaGetSymbolAddress((void**)&pxh, g_xh);   cudaGetSymbolAddress((void**)&pxl, g_xl);
    cudaGetSymbolAddress((void**)&pwqh, g_wqh); cudaGetSymbolAddress((void**)&pwql, g_wql);
    cudaGetSymbolAddress((void**)&pwoh, g_woh); cudaGetSymbolAddress((void**)&pwol, g_wol);
    cudaGetSymbolAddress((void**)&pqn, g_qn);
    cudaGetSymbolAddress((void**)&pkh, g_kh);
    cudaGetSymbolAddress((void**)&pvh, g_vh);
    cudaGetSymbolAddress((void**)&py, g_y);

    cudaFuncSetAttribute(mma_gemm_q, cudaFuncAttributeMaxDynamicSharedMemorySize, SMEM_TOT);
    cudaFuncSetAttribute(mma_gemm_o, cudaFuncAttributeMaxDynamicSharedMemorySize, SMEMH_TOT);
    cudaFuncSetAttribute(fused_attn, cudaFuncAttributeMaxDynamicSharedMemorySize, FA_TOT);

    // prep
    split4_kernel<<<(S_LEN * DM / 4 + 255) / 256, 256>>>(x, pxh, pxl, S_LEN * DM / 4);
    transpose_split_kernel<<<dim3(DM / 32, DM / 32), dim3(32, 8)>>>(Wq, pwqh, pwql, DM, DM);
    transpose_split_h_kernel<<<dim3(DM / 32, DM / 32), dim3(32, 8)>>>(Wo, pwoh, pwol, DM, DM);
    prep_k_kernel<<<(NK * NH) / 8, 256>>>(keys, scale, pkh);
    prep_v_kernel<<<dim3(NK / 32, HD / 32, NH), dim3(32, 8)>>>(values, pvh);

    // 1) q = normalize(x @ Wq) -> fp16 (bf16 3-pass, norm fused in epilogue)
    mma_gemm_q<<<dim3(DM / 128, S_LEN / 128, 1), 256, SMEM_TOT>>>(
        pxh, pxl, pwqh, pwql, pqn, DM, DM, DM, DM);

    // 2) fused attention -> y fp16
    fused_attn<<<dim3(S_LEN / 64, NH), 128, FA_TOT>>>(pqn, pkh, pvh, py);

    // 3) out = y @ Wo (fp16 2-pass, fp32 out)
    mma_gemm_o<<<dim3(DM / 128, S_LEN / 128, 1), 256, SMEMH_TOT>>>(
        py, pwoh, pwol, out, DM, DM, DM, DM);
}

// round 15
// speedup vs baseline: 5.9287x; 1.1068x over previous
#include <cuda_runtime.h>
#include <cuda_bf16.h>
#include <cuda_fp16.h>
#include <cstdint>
#include <math.h>

#define S_LEN 4096
#define DM    1024
#define NH    8
#define HD    128
#define NK    2048
#define EPSN  1e-6f

// ---------------- scratch (device globals; no allocation allowed) -------------
__device__ __half g_x16[(size_t)S_LEN * DM];                 // x, fp16
__device__ __half g_wqh[(size_t)DM * DM], g_wql[(size_t)DM * DM];  // Wq^T fp16 hi/lo
__device__ __half g_woh[(size_t)DM * DM], g_wol[(size_t)DM * DM];  // Wo^T fp16 hi/lo
__device__ __half g_qn[(size_t)S_LEN * DM];                  // normalized q, fp16
__device__ __half g_kh[(size_t)NH * NK * HD];                // normalized*scaled K, fp16
__device__ __half g_vh[(size_t)NH * HD * NK];                // V^T, fp16
__device__ __half g_y[(size_t)S_LEN * DM];                   // attention out, fp16

// ---------------- helpers -----------------------------------------------------
__device__ __forceinline__ uint32_t s2u(const void* p) {
    uint32_t a;
    asm("{ .reg .u64 t; cvta.to.shared.u64 t, %1; cvt.u32.u64 %0, t; }" : "=r"(a) : "l"(p));
    return a;
}
__device__ __forceinline__ uint32_t packh2(float a, float b) {
    __half2 t = __floats2half2_rn(a, b);
    return reinterpret_cast<uint32_t&>(t);
}
__device__ __forceinline__ void cpasync16(uint32_t dst, const void* src) {
    asm volatile("cp.async.cg.shared.global [%0], [%1], 16;" :: "r"(dst), "l"(src));
}
__device__ __forceinline__ void ldsm4(uint32_t* r, uint32_t addr) {
    asm volatile("ldmatrix.sync.aligned.m8n8.x4.shared.b16 {%0,%1,%2,%3}, [%4];"
        : "=r"(r[0]), "=r"(r[1]), "=r"(r[2]), "=r"(r[3]) : "r"(addr));
}
__device__ __forceinline__ void mma_h(float* c, const uint32_t* a, const uint32_t* b) {
    asm volatile("mma.sync.aligned.m16n8k16.row.col.f32.f16.f16.f32 "
        "{%0,%1,%2,%3}, {%4,%5,%6,%7}, {%8,%9}, {%0,%1,%2,%3};"
        : "+f"(c[0]), "+f"(c[1]), "+f"(c[2]), "+f"(c[3])
        : "r"(a[0]), "r"(a[1]), "r"(a[2]), "r"(a[3]), "r"(b[0]), "r"(b[1]));
}

#define ROWB  80
#define TILEB (128 * ROWB)
#define SMEMH_TOT (6 * TILEB)

// ---------------- fp16 2-pass GEMM: C = A * (Bh + Bl)^T -----------------------
// A fp16 single [M][K]; B fp16 hi/lo [N][K].
// EPI 0: fp32 store. EPI 3: per-row L2-normalize over the 128-col tile (= one
// head segment), store fp16 (q-projection).
template <int EPI>
__global__ void __launch_bounds__(256, 2)
mma_gemm_h(const __half* __restrict__ A,
           const __half* __restrict__ Bh, const __half* __restrict__ Bl,
           void* __restrict__ C0, int K, int lda, int ldb, int ldc)
{
    extern __shared__ char smch[];
    const uint32_t smb = s2u(smch);
    const int tid = threadIdx.x, lane = tid & 31, wid = tid >> 5;
    const int warpM = wid & 1, warpN = wid >> 1;
    const int bm = blockIdx.y * 128, bn = blockIdx.x * 128;

    const __half* src[3];
    src[0] = A + (long long)bm * lda;
    src[1] = Bh + (long long)bn * ldb;
    src[2] = Bl + (long long)bn * ldb;

    const int aLR = (lane & 7) + ((lane >> 3) & 1) * 8;
    const int aLK = (lane >> 4) * 8;
    const int bLR = (lane & 7) + (lane >> 4) * 8;
    const int bLK = ((lane >> 3) & 1) * 8;
    int aOff[4], bOff[2];
    #pragma unroll
    for (int m = 0; m < 4; m++) aOff[m] = (warpM * 64 + m * 16 + aLR) * ROWB + aLK * 2;
    #pragma unroll
    for (int p = 0; p < 2; p++) bOff[p] = (warpN * 32 + p * 16 + bLR) * ROWB + bLK * 2;

    float acc[4][4][4] = {};
    const int nCh = K >> 5;

    auto load_stage = [&](int st, int k0) {
        #pragma unroll
        for (int w = 0; w < 3; w++) {
            const __half* s = src[w] + k0;
            const int ld = (w < 1) ? lda : ldb;
            const uint32_t dst = smb + (uint32_t)(st * 3 + w) * TILEB;
            #pragma unroll
            for (int i = 0; i < 2; i++) {
                const int u = tid + i * 256;
                const int row = u >> 2, c = u & 3;
                cpasync16(dst + row * ROWB + c * 16, s + (long long)row * ld + c * 8);
            }
        }
    };

    load_stage(0, 0);
    asm volatile("cp.async.commit_group;" ::: "memory");

    for (int t = 0; t < nCh; t++) {
        if (t + 1 < nCh) {
            load_stage((t + 1) & 1, (t + 1) * 32);
            asm volatile("cp.async.commit_group;" ::: "memory");
            asm volatile("cp.async.wait_group 1;" ::: "memory");
        } else {
            asm volatile("cp.async.wait_group 0;" ::: "memory");
        }
        __syncthreads();

        const uint32_t base = smb + (uint32_t)((t & 1) * 3) * TILEB;
        #pragma unroll
        for (int kk = 0; kk < 2; kk++) {
            uint32_t bh[8], bl[8];
            #pragma unroll
            for (int p = 0; p < 2; p++) {
                ldsm4(bh + 4 * p, base + 1 * TILEB + bOff[p] + kk * 32);
                ldsm4(bl + 4 * p, base + 2 * TILEB + bOff[p] + kk * 32);
            }
            #pragma unroll
            for (int m = 0; m < 4; m++) {
                uint32_t a[4];
                ldsm4(a, base + aOff[m] + kk * 32);
                #pragma unroll
                for (int n = 0; n < 4; n++) {
                    mma_h(acc[m][n], a, bh + 2 * n);
                    mma_h(acc[m][n], a, bl + 2 * n);
                }
            }
        }
        __syncthreads();
    }

    const int qr = lane >> 2, qc = (lane & 3) * 2;

    if (EPI == 0) {
        float* C = (float*)C0;
        #pragma unroll
        for (int m = 0; m < 4; m++) {
            const int r0 = bm + warpM * 64 + m * 16 + qr;
            const int r1 = r0 + 8;
            #pragma unroll
            for (int n = 0; n < 4; n++) {
                const int c = bn + warpN * 32 + n * 8 + qc;
                *reinterpret_cast<float2*>(C + (long long)r0 * ldc + c) =
                    make_float2(acc[m][n][0], acc[m][n][1]);
                *reinterpret_cast<float2*>(C + (long long)r1 * ldc + c) =
                    make_float2(acc[m][n][2], acc[m][n][3]);
            }
        }
    } else {
        // EPI 3: row L2-normalize across this 128-col tile (one head), fp16 out
        float* ssm = (float*)smch;
        if (tid < 128) ssm[tid] = 0.0f;
        __syncthreads();
        #pragma unroll
        for (int m = 0; m < 4; m++) {
            float p0 = 0.0f, p1 = 0.0f;
            #pragma unroll
            for (int n = 0; n < 4; n++) {
                p0 += acc[m][n][0] * acc[m][n][0] + acc[m][n][1] * acc[m][n][1];
                p1 += acc[m][n][2] * acc[m][n][2] + acc[m][n][3] * acc[m][n][3];
            }
            p0 += __shfl_xor_sync(0xffffffffu, p0, 1);
            p0 += __shfl_xor_sync(0xffffffffu, p0, 2);
            p1 += __shfl_xor_sync(0xffffffffu, p1, 1);
            p1 += __shfl_xor_sync(0xffffffffu, p1, 2);
            if ((lane & 3) == 0) {
                atomicAdd(ssm + warpM * 64 + m * 16 + qr, p0);
                atomicAdd(ssm + warpM * 64 + m * 16 + qr + 8, p1);
            }
        }
        __syncthreads();
        __half* Q = (__half*)C0;
        #pragma unroll
        for (int m = 0; m < 4; m++) {
            const int lr0 = warpM * 64 + m * 16 + qr, lr1 = lr0 + 8;
            const float i0 = rsqrtf(ssm[lr0] + EPSN);
            const float i1 = rsqrtf(ssm[lr1] + EPSN);
            const int r0 = bm + lr0, r1 = bm + lr1;
            #pragma unroll
            for (int n = 0; n < 4; n++) {
                const int c = bn + warpN * 32 + n * 8 + qc;
                *reinterpret_cast<uint32_t*>(Q + (long long)r0 * ldc + c) =
                    packh2(acc[m][n][0] * i0, acc[m][n][1] * i0);
                *reinterpret_cast<uint32_t*>(Q + (long long)r1 * ldc + c) =
                    packh2(acc[m][n][2] * i1, acc[m][n][3] * i1);
            }
        }
    }
}

// ---------------- fused attention: 64 q-rows, 128 threads, occupancy 2 --------
// Q,K,V single fp16. P stays in registers; exp+rowsum folded into PV loop.
#define PITCH 272
#define QMATB (64 * PITCH)
#define KVMATB (128 * PITCH)
#define FA_Q  0
#define FA_K  QMATB
#define FA_V  (QMATB + KVMATB)
#define FA_TOT (QMATB + 2 * KVMATB)   // 87040

__global__ void __launch_bounds__(128, 2)
fused_attn(const __half* __restrict__ qn, const __half* __restrict__ kh,
           const __half* __restrict__ vh, __half* __restrict__ y)
{
    extern __shared__ char smch[];
    const uint32_t smb = s2u(smch);
    const int tid = threadIdx.x, lane = tid & 31, wid = tid >> 5;
    const int bm = blockIdx.x * 64, h = blockIdx.y;
    const int row8 = tid >> 4, c16 = tid & 15;

    #pragma unroll
    for (int i = 0; i < 8; i++) {
        const int r = row8 + i * 8;
        cpasync16(smb + FA_Q + r * PITCH + c16 * 16,
                  qn + (size_t)(bm + r) * DM + h * HD + c16 * 8);
    }
    asm volatile("cp.async.commit_group;" ::: "memory");

    auto load_k = [&](int j) {
        const __half* s = kh + ((size_t)h * NK + j * 128) * HD;
        #pragma unroll
        for (int i = 0; i < 16; i++) {
            const int r = row8 + i * 8;
            cpasync16(smb + FA_K + r * PITCH + c16 * 16, s + (size_t)r * HD + c16 * 8);
        }
        asm volatile("cp.async.commit_group;" ::: "memory");
    };
    auto load_v = [&](int j) {
        const __half* s = vh + (size_t)h * HD * NK + j * 128;
        #pragma unroll
        for (int i = 0; i < 16; i++) {
            const int r = row8 + i * 8;
            cpasync16(smb + FA_V + r * PITCH + c16 * 16, s + (size_t)r * NK + c16 * 8);
        }
        asm volatile("cp.async.commit_group;" ::: "memory");
    };

    load_k(0);
    load_v(0);

    const int aLR = (lane & 7) + ((lane >> 3) & 1) * 8;
    const int aLK = (lane >> 4) * 8;
    const int bLR = (lane & 7) + (lane >> 4) * 8;
    const int bLK = ((lane >> 3) & 1) * 8;
    const uint32_t aBase = (uint32_t)(wid * 16 + aLR) * PITCH + aLK * 2;
    const uint32_t bBase = (uint32_t)bLR * PITCH + bLK * 2;

    float accy[16][4] = {};
    float s0 = 0.0f, s1 = 0.0f;

    for (int j = 0; j < 16; j++) {
        float accs[16][4] = {};

        asm volatile("cp.async.wait_group 1;" ::: "memory");   // K_j ready
        __syncthreads();

        #pragma unroll
        for (int t = 0; t < 8; t++) {
            uint32_t a[4];
            ldsm4(a, smb + FA_Q + aBase + t * 32);
            #pragma unroll
            for (int p = 0; p < 8; p++) {
                uint32_t b[4];
                ldsm4(b, smb + FA_K + (uint32_t)p * 16 * PITCH + bBase + t * 32);
                mma_h(accs[2 * p],     a, b);
                mma_h(accs[2 * p + 1], a, b + 2);
            }
        }
        __syncthreads();
        if (j + 1 < 16) load_k(j + 1);

        asm volatile("cp.async.wait_group 1;" ::: "memory");   // V_j ready
        __syncthreads();

        #pragma unroll
        for (int t = 0; t < 8; t++) {
            uint32_t pf[4];
            {
                float* e0 = accs[2 * t];
                float* e1 = accs[2 * t + 1];
                e0[0] = __expf(e0[0]); e0[1] = __expf(e0[1]);
                e0[2] = __expf(e0[2]); e0[3] = __expf(e0[3]);
                e1[0] = __expf(e1[0]); e1[1] = __expf(e1[1]);
                e1[2] = __expf(e1[2]); e1[3] = __expf(e1[3]);
                s0 += e0[0] + e0[1] + e1[0] + e1[1];
                s1 += e0[2] + e0[3] + e1[2] + e1[3];
                pf[0] = packh2(e0[0], e0[1]);
                pf[1] = packh2(e0[2], e0[3]);
                pf[2] = packh2(e1[0], e1[1]);
                pf[3] = packh2(e1[2], e1[3]);
            }
            #pragma unroll
            for (int p = 0; p < 8; p++) {
                uint32_t b[4];
                ldsm4(b, smb + FA_V + (uint32_t)p * 16 * PITCH + bBase + t * 32);
                mma_h(accy[2 * p],     pf, b);
                mma_h(accy[2 * p + 1], pf, b + 2);
            }
        }
        __syncthreads();
        if (j + 1 < 16) load_v(j + 1);
    }

    s0 += __shfl_xor_sync(0xffffffffu, s0, 1);
    s0 += __shfl_xor_sync(0xffffffffu, s0, 2);
    s1 += __shfl_xor_sync(0xffffffffu, s1, 1);
    s1 += __shfl_xor_sync(0xffffffffu, s1, 2);
    const float inv0 = 1.0f / s0, inv1 = 1.0f / s1;

    const int qr = lane >> 2, qc = (lane & 3) * 2;
    const int r0 = bm + wid * 16 + qr, r1 = r0 + 8;
    #pragma unroll
    for (int n = 0; n < 16; n++) {
        const int c = h * HD + n * 8 + qc;
        *reinterpret_cast<uint32_t*>(y + (size_t)r0 * DM + c) =
            packh2(accy[n][0] * inv0, accy[n][1] * inv0);
        *reinterpret_cast<uint32_t*>(y + (size_t)r1 * DM + c) =
            packh2(accy[n][2] * inv1, accy[n][3] * inv1);
    }
}

// ---------------- prep kernels ------------------------------------------------
// x -> fp16 (plain convert)
__global__ void cvt_h_kernel(const float* __restrict__ s, __half* __restrict__ d, int n4)
{
    const int i = blockIdx.x * 256 + threadIdx.x;
    if (i >= n4) return;
    float4 x = reinterpret_cast<const float4*>(s)[i];
    reinterpret_cast<uint2*>(d)[i] = make_uint2(packh2(x.x, x.y), packh2(x.z, x.w));
}

// transpose + fp16 hi/lo split (Wq, Wo)
__global__ void transpose_split_h_kernel(const float* __restrict__ W, __half* __restrict__ Th,
                                         __half* __restrict__ Tl, int R, int C)
{
    __shared__ float tile[32][33];
    const int r0 = blockIdx.y * 32, c0 = blockIdx.x * 32;
    for (int i = threadIdx.y; i < 32; i += 8)
        tile[i][threadIdx.x] = W[(long long)(r0 + i) * C + c0 + threadIdx.x];
    __syncthreads();
    for (int i = threadIdx.y; i < 32; i += 8) {
        float x = tile[threadIdx.x][i];
        __half hx = __float2half_rn(x);
        long long o = (long long)(c0 + i) * R + r0 + threadIdx.x;
        Th[o] = hx;
        Tl[o] = __float2half_rn(x - __half2float(hx));
    }
}

// keys: row n = k*NH+h -> normalized*scale, fp16, layout [h][k][d]
__global__ void prep_k_kernel(const float* __restrict__ keys, const float* __restrict__ scale,
                              __half* __restrict__ kout)
{
    const int seg = blockIdx.x * 8 + (threadIdx.x >> 5);
    const int lane = threadIdx.x & 31;
    const int k = seg / NH, h = seg % NH;
    float4 x = reinterpret_cast<const float4*>(keys + (size_t)seg * HD)[lane];
    float ss = x.x * x.x + x.y * x.y + x.z * x.z + x.w * x.w;
    #pragma unroll
    for (int o = 16; o > 0; o >>= 1) ss += __shfl_xor_sync(0xffffffffu, ss, o);
    const float rr = rsqrtf(ss + EPSN) * scale[h];
    const size_t base = ((size_t)h * NK + k) * HD;
    reinterpret_cast<uint2*>(kout + base)[lane] =
        make_uint2(packh2(x.x * rr, x.y * rr), packh2(x.z * rr, x.w * rr));
}

// values: [k][h][d] -> vT[h][d][k], fp16
__global__ void prep_v_kernel(const float* __restrict__ values, __half* __restrict__ vout)
{
    __shared__ float tile[32][33];
    const int h = blockIdx.z, k0 = blockIdx.x * 32, d0 = blockIdx.y * 32;
    for (int i = threadIdx.y; i < 32; i += 8)
        tile[i][threadIdx.x] = values[((size_t)(k0 + i) * NH + h) * HD + d0 + threadIdx.x];
    __syncthreads();
    for (int i = threadIdx.y; i < 32; i += 8) {
        size_t o = ((size_t)h * HD + d0 + i) * NK + k0 + threadIdx.x;
        vout[o] = __float2half_rn(tile[threadIdx.x][i]);
    }
}

// ---------------- launch ------------------------------------------------------
extern "C" void kernel_launch(void* const* d_in, const int* in_sizes, int n_in,
                              void* d_out, int out_size)
{
    const float* x      = (const float*)d_in[0];
    const float* Wq     = (const float*)d_in[1];
    const float* keys   = (const float*)d_in[2];
    const float* values = (const float*)d_in[3];
    const float* scale  = (const float*)d_in[4];
    const float* Wo     = (const float*)d_in[5];
    float* out = (float*)d_out;

    __half *px16, *pwqh, *pwql, *pwoh, *pwol, *pqn, *pkh, *pvh, *py;
    cudaGetSymbolAddress((void**)&px16, g_x16);
    cudaGetSymbolAddress((void**)&pwqh, g_wqh); cudaGetSymbolAddress((void**)&pwql, g_wql);
    cudaGetSymbolAddress((void**)&pwoh, g_woh); cudaGetSymbolAddress((void**)&pwol, g_wol);
    cudaGetSymbolAddress((void**)&pqn, g_qn);
    cudaGetSymbolAddress((void**)&pkh, g_kh);
    cudaGetSymbolAddress((void**)&pvh, g_vh);
    cudaGetSymbolAddress((void**)&py, g_y);

    cudaFuncSetAttribute(mma_gemm_h<0>, cudaFuncAttributeMaxDynamicSharedMemorySize, SMEMH_TOT);
    cudaFuncSetAttribute(mma_gemm_h<3>, cudaFuncAttributeMaxDynamicSharedMemorySize, SMEMH_TOT);
    cudaFuncSetAttribute(fused_attn, cudaFuncAttributeMaxDynamicSharedMemorySize, FA_TOT);

    // prep
    cvt_h_kernel<<<(S_LEN * DM / 4 + 255) / 256, 256>>>(x, px16, S_LEN * DM / 4);
    transpose_split_h_kernel<<<dim3(DM / 32, DM / 32), dim3(32, 8)>>>(Wq, pwqh, pwql, DM, DM);
    transpose_split_h_kernel<<<dim3(DM / 32, DM / 32), dim3(32, 8)>>>(Wo, pwoh, pwol, DM, DM);
    prep_k_kernel<<<(NK * NH) / 8, 256>>>(keys, scale, pkh);
    prep_v_kernel<<<dim3(NK / 32, HD / 32, NH), dim3(32, 8)>>>(values, pvh);

    // 1) q = normalize(x @ Wq) -> fp16 (fp16 2-pass, norm fused in epilogue)
    mma_gemm_h<3><<<dim3(DM / 128, S_LEN / 128, 1), 256, SMEMH_TOT>>>(
        px16, pwqh, pwql, pqn, DM, DM, DM, DM);

    // 2) fused attention -> y fp16
    fused_attn<<<dim3(S_LEN / 64, NH), 128, FA_TOT>>>(pqn, pkh, pvh, py);

    // 3) out = y @ Wo (fp16 2-pass, fp32 out)
    mma_gemm_h<0><<<dim3(DM / 128, S_LEN / 128, 1), 256, SMEMH_TOT>>>(
        py, pwoh, pwol, out, DM, DM, DM, DM);
}

// round 16
// speedup vs baseline: 6.0650x; 1.0230x over previous
#include <cuda_runtime.h>
#include <cuda_bf16.h>
#include <cuda_fp16.h>
#include <cstdint>
#include <math.h>

#define S_LEN 4096
#define DM    1024
#define NH    8
#define HD    128
#define NK    2048
#define EPSN  1e-6f

// ---------------- scratch (device globals; no allocation allowed) -------------
__device__ __half g_x16[(size_t)S_LEN * DM];                 // x, fp16
__device__ __half g_wqh[(size_t)DM * DM], g_wql[(size_t)DM * DM];  // Wq^T fp16 hi/lo
__device__ __half g_woh[(size_t)DM * DM], g_wol[(size_t)DM * DM];  // Wo^T fp16 hi/lo
__device__ __half g_qn[(size_t)S_LEN * DM];                  // normalized q, fp16
__device__ __half g_kh[(size_t)NH * NK * HD];                // normalized*scaled K, fp16
__device__ __half g_vh[(size_t)NH * HD * NK];                // V^T, fp16
__device__ __half g_y[(size_t)S_LEN * DM];                   // attention out, fp16

// ---------------- helpers -----------------------------------------------------
__device__ __forceinline__ uint32_t s2u(const void* p) {
    uint32_t a;
    asm("{ .reg .u64 t; cvta.to.shared.u64 t, %1; cvt.u32.u64 %0, t; }" : "=r"(a) : "l"(p));
    return a;
}
__device__ __forceinline__ uint32_t packh2(float a, float b) {
    __half2 t = __floats2half2_rn(a, b);
    return reinterpret_cast<uint32_t&>(t);
}
__device__ __forceinline__ void cpasync16(uint32_t dst, const void* src) {
    asm volatile("cp.async.cg.shared.global [%0], [%1], 16;" :: "r"(dst), "l"(src));
}
__device__ __forceinline__ void ldsm4(uint32_t* r, uint32_t addr) {
    asm volatile("ldmatrix.sync.aligned.m8n8.x4.shared.b16 {%0,%1,%2,%3}, [%4];"
        : "=r"(r[0]), "=r"(r[1]), "=r"(r[2]), "=r"(r[3]) : "r"(addr));
}
__device__ __forceinline__ void mma_h(float* c, const uint32_t* a, const uint32_t* b) {
    asm volatile("mma.sync.aligned.m16n8k16.row.col.f32.f16.f16.f32 "
        "{%0,%1,%2,%3}, {%4,%5,%6,%7}, {%8,%9}, {%0,%1,%2,%3};"
        : "+f"(c[0]), "+f"(c[1]), "+f"(c[2]), "+f"(c[3])
        : "r"(a[0]), "r"(a[1]), "r"(a[2]), "r"(a[3]), "r"(b[0]), "r"(b[1]));
}
#define CP_COMMIT() asm volatile("cp.async.commit_group;" ::: "memory")

#define ROWB  80
#define TILEB (128 * ROWB)
#define SMEMH_TOT (6 * TILEB)

// ---------------- fp16 2-pass GEMM: C = A * (Bh + Bl)^T -----------------------
// EPI 0: fp32 store. EPI 3: per-row L2-normalize over the 128-col tile, fp16 out.
template <int EPI>
__global__ void __launch_bounds__(256, 2)
mma_gemm_h(const __half* __restrict__ A,
           const __half* __restrict__ Bh, const __half* __restrict__ Bl,
           void* __restrict__ C0, int K, int lda, int ldb, int ldc)
{
    extern __shared__ char smch[];
    const uint32_t smb = s2u(smch);
    const int tid = threadIdx.x, lane = tid & 31, wid = tid >> 5;
    const int warpM = wid & 1, warpN = wid >> 1;
    const int bm = blockIdx.y * 128, bn = blockIdx.x * 128;

    const __half* src[3];
    src[0] = A + (long long)bm * lda;
    src[1] = Bh + (long long)bn * ldb;
    src[2] = Bl + (long long)bn * ldb;

    const int aLR = (lane & 7) + ((lane >> 3) & 1) * 8;
    const int aLK = (lane >> 4) * 8;
    const int bLR = (lane & 7) + (lane >> 4) * 8;
    const int bLK = ((lane >> 3) & 1) * 8;
    int aOff[4], bOff[2];
    #pragma unroll
    for (int m = 0; m < 4; m++) aOff[m] = (warpM * 64 + m * 16 + aLR) * ROWB + aLK * 2;
    #pragma unroll
    for (int p = 0; p < 2; p++) bOff[p] = (warpN * 32 + p * 16 + bLR) * ROWB + bLK * 2;

    float acc[4][4][4] = {};
    const int nCh = K >> 5;

    auto load_stage = [&](int st, int k0) {
        #pragma unroll
        for (int w = 0; w < 3; w++) {
            const __half* s = src[w] + k0;
            const int ld = (w < 1) ? lda : ldb;
            const uint32_t dst = smb + (uint32_t)(st * 3 + w) * TILEB;
            #pragma unroll
            for (int i = 0; i < 2; i++) {
                const int u = tid + i * 256;
                const int row = u >> 2, c = u & 3;
                cpasync16(dst + row * ROWB + c * 16, s + (long long)row * ld + c * 8);
            }
        }
    };

    load_stage(0, 0);
    CP_COMMIT();

    for (int t = 0; t < nCh; t++) {
        if (t + 1 < nCh) {
            load_stage((t + 1) & 1, (t + 1) * 32);
            CP_COMMIT();
            asm volatile("cp.async.wait_group 1;" ::: "memory");
        } else {
            asm volatile("cp.async.wait_group 0;" ::: "memory");
        }
        __syncthreads();

        const uint32_t base = smb + (uint32_t)((t & 1) * 3) * TILEB;
        #pragma unroll
        for (int kk = 0; kk < 2; kk++) {
            uint32_t bh[8], bl[8];
            #pragma unroll
            for (int p = 0; p < 2; p++) {
                ldsm4(bh + 4 * p, base + 1 * TILEB + bOff[p] + kk * 32);
                ldsm4(bl + 4 * p, base + 2 * TILEB + bOff[p] + kk * 32);
            }
            #pragma unroll
            for (int m = 0; m < 4; m++) {
                uint32_t a[4];
                ldsm4(a, base + aOff[m] + kk * 32);
                #pragma unroll
                for (int n = 0; n < 4; n++) {
                    mma_h(acc[m][n], a, bh + 2 * n);
                    mma_h(acc[m][n], a, bl + 2 * n);
                }
            }
        }
        __syncthreads();
    }

    const int qr = lane >> 2, qc = (lane & 3) * 2;

    if (EPI == 0) {
        float* C = (float*)C0;
        #pragma unroll
        for (int m = 0; m < 4; m++) {
            const int r0 = bm + warpM * 64 + m * 16 + qr;
            const int r1 = r0 + 8;
            #pragma unroll
            for (int n = 0; n < 4; n++) {
                const int c = bn + warpN * 32 + n * 8 + qc;
                *reinterpret_cast<float2*>(C + (long long)r0 * ldc + c) =
                    make_float2(acc[m][n][0], acc[m][n][1]);
                *reinterpret_cast<float2*>(C + (long long)r1 * ldc + c) =
                    make_float2(acc[m][n][2], acc[m][n][3]);
            }
        }
    } else {
        float* ssm = (float*)smch;
        if (tid < 128) ssm[tid] = 0.0f;
        __syncthreads();
        #pragma unroll
        for (int m = 0; m < 4; m++) {
            float p0 = 0.0f, p1 = 0.0f;
            #pragma unroll
            for (int n = 0; n < 4; n++) {
                p0 += acc[m][n][0] * acc[m][n][0] + acc[m][n][1] * acc[m][n][1];
                p1 += acc[m][n][2] * acc[m][n][2] + acc[m][n][3] * acc[m][n][3];
            }
            p0 += __shfl_xor_sync(0xffffffffu, p0, 1);
            p0 += __shfl_xor_sync(0xffffffffu, p0, 2);
            p1 += __shfl_xor_sync(0xffffffffu, p1, 1);
            p1 += __shfl_xor_sync(0xffffffffu, p1, 2);
            if ((lane & 3) == 0) {
                atomicAdd(ssm + warpM * 64 + m * 16 + qr, p0);
                atomicAdd(ssm + warpM * 64 + m * 16 + qr + 8, p1);
            }
        }
        __syncthreads();
        __half* Q = (__half*)C0;
        #pragma unroll
        for (int m = 0; m < 4; m++) {
            const int lr0 = warpM * 64 + m * 16 + qr, lr1 = lr0 + 8;
            const float i0 = rsqrtf(ssm[lr0] + EPSN);
            const float i1 = rsqrtf(ssm[lr1] + EPSN);
            const int r0 = bm + lr0, r1 = bm + lr1;
            #pragma unroll
            for (int n = 0; n < 4; n++) {
                const int c = bn + warpN * 32 + n * 8 + qc;
                *reinterpret_cast<uint32_t*>(Q + (long long)r0 * ldc + c) =
                    packh2(acc[m][n][0] * i0, acc[m][n][1] * i0);
                *reinterpret_cast<uint32_t*>(Q + (long long)r1 * ldc + c) =
                    packh2(acc[m][n][2] * i1, acc[m][n][3] * i1);
            }
        }
    }
}

// ---------------- fused attention: 64 q-rows, 64-slot KV tiles, K/V double-buf -
// Q,K,V single fp16. 32 KV tiles of 64 slots; K and V double-buffered so 2
// tiles are always in flight. P stays in registers; exp+rowsum in PV loop.
#define PITCH  272                  // Q/K rows: 128 halves + pad (17x16B)
#define VPITCH 144                  // V rows: 64 halves + pad (9x16B)
#define QSZ  (64 * PITCH)           // 17408
#define KSZ  (64 * PITCH)           // 17408
#define VSZ  (128 * VPITCH)         // 18432
#define FA_Q  0
#define FA_K0 QSZ
#define FA_K1 (QSZ + KSZ)
#define FA_V0 (QSZ + 2 * KSZ)
#define FA_V1 (QSZ + 2 * KSZ + VSZ)
#define FA_TOT (QSZ + 2 * KSZ + 2 * VSZ)   // 89088

__global__ void __launch_bounds__(128, 2)
fused_attn(const __half* __restrict__ qn, const __half* __restrict__ kh,
           const __half* __restrict__ vh, __half* __restrict__ y)
{
    extern __shared__ char smch[];
    const uint32_t smb = s2u(smch);
    const int tid = threadIdx.x, lane = tid & 31, wid = tid >> 5;
    const int bm = blockIdx.x * 64, h = blockIdx.y;

    // Q tile: 64 rows x 256 B  (128 threads: 8 rows x 16 chunks)
    {
        const int r8 = tid >> 4, c16 = tid & 15;
        #pragma unroll
        for (int i = 0; i < 8; i++) {
            const int r = r8 + i * 8;
            cpasync16(smb + FA_Q + r * PITCH + c16 * 16,
                      qn + (size_t)(bm + r) * DM + h * HD + c16 * 8);
        }
        CP_COMMIT();
    }

    auto load_k = [&](int j) {   // 64 slots x 256 B
        const __half* s = kh + ((size_t)h * NK + j * 64) * HD;
        const uint32_t dst = smb + ((j & 1) ? FA_K1 : FA_K0);
        const int r8 = tid >> 4, c16 = tid & 15;
        #pragma unroll
        for (int i = 0; i < 8; i++) {
            const int r = r8 + i * 8;
            cpasync16(dst + r * PITCH + c16 * 16, s + (size_t)r * HD + c16 * 8);
        }
        CP_COMMIT();
    };
    auto load_v = [&](int j) {   // 128 d-rows x 128 B
        const __half* s = vh + (size_t)h * HD * NK + j * 64;
        const uint32_t dst = smb + ((j & 1) ? FA_V1 : FA_V0);
        const int r16 = tid >> 3, c8 = tid & 7;
        #pragma unroll
        for (int i = 0; i < 8; i++) {
            const int r = r16 + i * 16;
            cpasync16(dst + r * VPITCH + c8 * 16, s + (size_t)r * NK + c8 * 8);
        }
        CP_COMMIT();
    };

    load_k(0); load_v(0); load_k(1); load_v(1);
    // commit order: Q, K0, V0, K1, V1; steady state keeps 2 KV tiles in flight.

    const int aLR = (lane & 7) + ((lane >> 3) & 1) * 8;
    const int aLK = (lane >> 4) * 8;
    const int bLR = (lane & 7) + (lane >> 4) * 8;
    const int bLK = ((lane >> 3) & 1) * 8;
    const uint32_t aBase  = (uint32_t)(wid * 16 + aLR) * PITCH + aLK * 2;
    const uint32_t bBaseK = (uint32_t)bLR * PITCH + bLK * 2;
    const uint32_t bBaseV = (uint32_t)bLR * VPITCH + bLK * 2;

    float accy[16][4] = {};
    float s0 = 0.0f, s1 = 0.0f;

    for (int j = 0; j < 32; j++) {
        const uint32_t kbuf = smb + ((j & 1) ? FA_K1 : FA_K0);
        const uint32_t vbuf = smb + ((j & 1) ? FA_V1 : FA_V0);
        float accs[8][4] = {};

        // K_j ready: all except the 3 most recent (V_{j+1},K_{j+1},V_j);
        // tail j=31: only V31 after K31.
        if (j < 31) asm volatile("cp.async.wait_group 3;" ::: "memory");
        else        asm volatile("cp.async.wait_group 1;" ::: "memory");
        __syncthreads();

        // ---- S = Q * K_j^T ----
        #pragma unroll
        for (int t = 0; t < 8; t++) {
            uint32_t a[4];
            ldsm4(a, smb + FA_Q + aBase + t * 32);
            #pragma unroll
            for (int p = 0; p < 4; p++) {
                uint32_t b[4];
                ldsm4(b, kbuf + (uint32_t)p * 16 * PITCH + bBaseK + t * 32);
                mma_h(accs[2 * p],     a, b);
                mma_h(accs[2 * p + 1], a, b + 2);
            }
        }
        __syncthreads();
        if (j + 2 < 32) load_k(j + 2);

        // V_j ready: j<=29 → 3 recent are (K_{j+2},V_{j+1},K_{j+1});
        // j=30 → (V31,K31); j=31 → none.
        if (j < 30)      asm volatile("cp.async.wait_group 3;" ::: "memory");
        else if (j == 30) asm volatile("cp.async.wait_group 2;" ::: "memory");
        else             asm volatile("cp.async.wait_group 0;" ::: "memory");
        __syncthreads();

        // ---- y += P * V_j; exp + rowsum folded per t ----
        #pragma unroll
        for (int t = 0; t < 4; t++) {
            uint32_t pf[4];
            {
                float* e0 = accs[2 * t];
                float* e1 = accs[2 * t + 1];
                e0[0] = __expf(e0[0]); e0[1] = __expf(e0[1]);
                e0[2] = __expf(e0[2]); e0[3] = __expf(e0[3]);
                e1[0] = __expf(e1[0]); e1[1] = __expf(e1[1]);
                e1[2] = __expf(e1[2]); e1[3] = __expf(e1[3]);
                s0 += e0[0] + e0[1] + e1[0] + e1[1];
                s1 += e0[2] + e0[3] + e1[2] + e1[3];
                pf[0] = packh2(e0[0], e0[1]);
                pf[1] = packh2(e0[2], e0[3]);
                pf[2] = packh2(e1[0], e1[1]);
                pf[3] = packh2(e1[2], e1[3]);
            }
            #pragma unroll
            for (int p = 0; p < 8; p++) {
                uint32_t b[4];
                ldsm4(b, vbuf + (uint32_t)p * 16 * VPITCH + bBaseV + t * 32);
                mma_h(accy[2 * p],     pf, b);
                mma_h(accy[2 * p + 1], pf, b + 2);
            }
        }
        __syncthreads();
        if (j + 2 < 32) load_v(j + 2);
    }

    // ---- epilogue: /rowsum, write fp16 ----
    s0 += __shfl_xor_sync(0xffffffffu, s0, 1);
    s0 += __shfl_xor_sync(0xffffffffu, s0, 2);
    s1 += __shfl_xor_sync(0xffffffffu, s1, 1);
    s1 += __shfl_xor_sync(0xffffffffu, s1, 2);
    const float inv0 = 1.0f / s0, inv1 = 1.0f / s1;

    const int qr = lane >> 2, qc = (lane & 3) * 2;
    const int r0 = bm + wid * 16 + qr, r1 = r0 + 8;
    #pragma unroll
    for (int n = 0; n < 16; n++) {
        const int c = h * HD + n * 8 + qc;
        *reinterpret_cast<uint32_t*>(y + (size_t)r0 * DM + c) =
            packh2(accy[n][0] * inv0, accy[n][1] * inv0);
        *reinterpret_cast<uint32_t*>(y + (size_t)r1 * DM + c) =
            packh2(accy[n][2] * inv1, accy[n][3] * inv1);
    }
}

// ---------------- prep kernels ------------------------------------------------
__global__ void cvt_h_kernel(const float* __restrict__ s, __half* __restrict__ d, int n4)
{
    const int i = blockIdx.x * 256 + threadIdx.x;
    if (i >= n4) return;
    float4 x = reinterpret_cast<const float4*>(s)[i];
    reinterpret_cast<uint2*>(d)[i] = make_uint2(packh2(x.x, x.y), packh2(x.z, x.w));
}

// both weight transposes in one launch: blockIdx.z selects (Wq) vs (Wo)
__global__ void transpose_split2_kernel(const float* __restrict__ W0, __half* __restrict__ T0h,
                                        __half* __restrict__ T0l,
                                        const float* __restrict__ W1, __half* __restrict__ T1h,
                                        __half* __restrict__ T1l)
{
    const float* W = blockIdx.z ? W1 : W0;
    __half* Th = blockIdx.z ? T1h : T0h;
    __half* Tl = blockIdx.z ? T1l : T0l;
    __shared__ float tile[32][33];
    const int r0 = blockIdx.y * 32, c0 = blockIdx.x * 32;
    for (int i = threadIdx.y; i < 32; i += 8)
        tile[i][threadIdx.x] = W[(long long)(r0 + i) * DM + c0 + threadIdx.x];
    __syncthreads();
    for (int i = threadIdx.y; i < 32; i += 8) {
        float x = tile[threadIdx.x][i];
        __half hx = __float2half_rn(x);
        long long o = (long long)(c0 + i) * DM + r0 + threadIdx.x;
        Th[o] = hx;
        Tl[o] = __float2half_rn(x - __half2float(hx));
    }
}

__global__ void prep_k_kernel(const float* __restrict__ keys, const float* __restrict__ scale,
                              __half* __restrict__ kout)
{
    const int seg = blockIdx.x * 8 + (threadIdx.x >> 5);
    const int lane = threadIdx.x & 31;
    const int k = seg / NH, h = seg % NH;
    float4 x = reinterpret_cast<const float4*>(keys + (size_t)seg * HD)[lane];
    float ss = x.x * x.x + x.y * x.y + x.z * x.z + x.w * x.w;
    #pragma unroll
    for (int o = 16; o > 0; o >>= 1) ss += __shfl_xor_sync(0xffffffffu, ss, o);
    const float rr = rsqrtf(ss + EPSN) * scale[h];
    const size_t base = ((size_t)h * NK + k) * HD;
    reinterpret_cast<uint2*>(kout + base)[lane] =
        make_uint2(packh2(x.x * rr, x.y * rr), packh2(x.z * rr, x.w * rr));
}

__global__ void prep_v_kernel(const float* __restrict__ values, __half* __restrict__ vout)
{
    __shared__ float tile[32][33];
    const int h = blockIdx.z, k0 = blockIdx.x * 32, d0 = blockIdx.y * 32;
    for (int i = threadIdx.y; i < 32; i += 8)
        tile[i][threadIdx.x] = values[((size_t)(k0 + i) * NH + h) * HD + d0 + threadIdx.x];
    __syncthreads();
    for (int i = threadIdx.y; i < 32; i += 8) {
        size_t o = ((size_t)h * HD + d0 + i) * NK + k0 + threadIdx.x;
        vout[o] = __float2half_rn(tile[threadIdx.x][i]);
    }
}

// ---------------- launch ------------------------------------------------------
extern "C" void kernel_launch(void* const* d_in, const int* in_sizes, int n_in,
                              void* d_out, int out_size)
{
    const float* x      = (const float*)d_in[0];
    const float* Wq     = (const float*)d_in[1];
    const float* keys   = (const float*)d_in[2];
    const float* values = (const float*)d_in[3];
    const float* scale  = (const float*)d_in[4];
    const float* Wo     = (const float*)d_in[5];
    float* out = (float*)d_out;

    __half *px16, *pwqh, *pwql, *pwoh, *pwol, *pqn, *pkh, *pvh, *py;
    cudaGetSymbolAddress((void**)&px16, g_x16);
    cudaGetSymbolAddress((void**)&pwqh, g_wqh); cudaGetSymbolAddress((void**)&pwql, g_wql);
    cudaGetSymbolAddress((void**)&pwoh, g_woh); cudaGetSymbolAddress((void**)&pwol, g_wol);
    cudaGetSymbolAddress((void**)&pqn, g_qn);
    cudaGetSymbolAddress((void**)&pkh, g_kh);
    cudaGetSymbolAddress((void**)&pvh, g_vh);
    cudaGetSymbolAddress((void**)&py, g_y);

    cudaFuncSetAttribute(mma_gemm_h<0>, cudaFuncAttributeMaxDynamicSharedMemorySize, SMEMH_TOT);
    cudaFuncSetAttribute(mma_gemm_h<3>, cudaFuncAttributeMaxDynamicSharedMemorySize, SMEMH_TOT);
    cudaFuncSetAttribute(fused_attn, cudaFuncAttributeMaxDynamicSharedMemorySize, FA_TOT);

    // prep
    cvt_h_kernel<<<(S_LEN * DM / 4 + 255) / 256, 256>>>(x, px16, S_LEN * DM / 4);
    transpose_split2_kernel<<<dim3(DM / 32, DM / 32, 2), dim3(32, 8)>>>(
        Wq, pwqh, pwql, Wo, pwoh, pwol);
    prep_k_kernel<<<(NK * NH) / 8, 256>>>(keys, scale, pkh);
    prep_v_kernel<<<dim3(NK / 32, HD / 32, NH), dim3(32, 8)>>>(values, pvh);

    // 1) q = normalize(x @ Wq) -> fp16 (fp16 2-pass, norm fused in epilogue)
    mma_gemm_h<3><<<dim3(DM / 128, S_LEN / 128, 1), 256, SMEMH_TOT>>>(
        px16, pwqh, pwql, pqn, DM, DM, DM, DM);

    // 2) fused attention -> y fp16
    fused_attn<<<dim3(S_LEN / 64, NH), 128, FA_TOT>>>(pqn, pkh, pvh, py);

    // 3) out = y @ Wo (fp16 2-pass, fp32 out)
    mma_gemm_h<0><<<dim3(DM / 128, S_LEN / 128, 1), 256, SMEMH_TOT>>>(
        py, pwoh, pwol, out, DM, DM, DM, DM);
}